// round 6
// baseline (speedup 1.0000x reference)
#include <cuda_runtime.h>
#include <cuda_bf16.h>
#include <math.h>
#include <stdint.h>

// ---------------- problem constants ----------------
#define NL_LAYERS 3
#define N_HEADS   16
#define EMB       1024
#define HEAD_DIM  64
#define SEQ_T     1024
#define BATCH     4
#define ROWS      (BATCH * SEQ_T)      // 4096
#define VOCAB     32000
#define E3        (3 * EMB)            // 3072
#define FF_DIM    (4 * EMB)            // 4096
#define LN_EPS    1e-5f
#define ATT_SCALE 0.03125f             // 1/sqrt(EMB) = 1/32

// ---------------- scratch (device globals; no allocation allowed) ----------------
__device__ float g_x   [ROWS * EMB];
__device__ float g_h   [ROWS * EMB];
__device__ float g_qkv [ROWS * E3];
__device__ float g_att [ROWS * EMB];
__device__ float g_ff  [ROWS * FF_DIM];
__device__ float g_wqkv[NL_LAYERS * EMB * E3];       // prepacked + tf32-rounded
__device__ float g_wo  [NL_LAYERS * EMB * EMB];      // tf32-rounded copies
__device__ float g_w1  [NL_LAYERS * EMB * FF_DIM];
__device__ float g_w2  [NL_LAYERS * FF_DIM * EMB];
__device__ float g_lmw [EMB * VOCAB];
__device__ float g_logits[(size_t)ROWS * VOCAB];
__device__ float g_rowloss[ROWS];

// ---------------- tf32 helpers ----------------
__device__ __forceinline__ unsigned int f2tf32(float f) {
    unsigned int u;
    asm("cvt.rna.tf32.f32 %0, %1;" : "=r"(u) : "f"(f));
    return u;
}
__device__ __forceinline__ float tf32r(float f) {
    return __uint_as_float(f2tf32(f));
}

#define MMA_TF32(d, a, b)                                                     \
    asm volatile("mma.sync.aligned.m16n8k8.row.col.f32.tf32.tf32.f32 "        \
                 "{%0,%1,%2,%3}, {%4,%5,%6,%7}, {%8,%9}, {%0,%1,%2,%3};"      \
                 : "+f"(d[0]), "+f"(d[1]), "+f"(d[2]), "+f"(d[3])             \
                 : "r"(a[0]), "r"(a[1]), "r"(a[2]), "r"(a[3]),                \
                   "r"(b[0]), "r"(b[1]))

#define CP_ASYNC16(dst, src)                                                  \
    asm volatile("cp.async.cg.shared.global [%0], [%1], 16;" ::               \
                 "r"(dst), "l"(src))
#define CP_COMMIT() asm volatile("cp.async.commit_group;")
#define CP_WAIT(n)  asm volatile("cp.async.wait_group %0;" :: "n"(n))

// ---------------- prepack wq/wk/wv -> [l][e][3E] (tf32-rounded) ----------------
__global__ void prepack_qkv(const float* __restrict__ wq,
                            const float* __restrict__ wk,
                            const float* __restrict__ wv) {
    int idx = blockIdx.x * blockDim.x + threadIdx.x;
    int total = NL_LAYERS * EMB * E3;
    if (idx >= total) return;
    int l = idx / (EMB * E3);
    int r = idx % (EMB * E3);
    int e = r / E3;
    int c = r % E3;
    float v;
    if (c < EMB) {
        int h = c >> 6, d = c & 63;
        v = wq[(((size_t)l * N_HEADS + h) * EMB + e) * HEAD_DIM + d];
    } else if (c < 2 * EMB) {
        int c2 = c - EMB; int h = c2 >> 6, d = c2 & 63;
        v = wk[(((size_t)l * N_HEADS + h) * EMB + e) * HEAD_DIM + d];
    } else {
        int c2 = c - 2 * EMB; int h = c2 >> 6, d = c2 & 63;
        v = wv[(((size_t)l * N_HEADS + h) * EMB + e) * HEAD_DIM + d];
    }
    g_wqkv[idx] = tf32r(v);
}

// ---------------- generic tf32-rounding copy (float4) ----------------
__global__ void cvt_kernel(const float* __restrict__ src, float* __restrict__ dst,
                           int n4) {
    int i = blockIdx.x * blockDim.x + threadIdx.x;
    if (i >= n4) return;
    float4 v = ((const float4*)src)[i];
    v.x = tf32r(v.x); v.y = tf32r(v.y); v.z = tf32r(v.z); v.w = tf32r(v.w);
    ((float4*)dst)[i] = v;
}

// ---------------- embedding ----------------
__global__ void embed_kernel(const int* __restrict__ ids,
                             const float* __restrict__ tok_emb,
                             const float* __restrict__ pos_emb) {
    int idx = blockIdx.x * blockDim.x + threadIdx.x;
    if (idx >= ROWS * EMB) return;
    int row = idx >> 10;
    int e   = idx & 1023;
    int t   = row & (SEQ_T - 1);
    int tok = ids[row];
    g_x[idx] = tok_emb[(size_t)tok * EMB + e] + pos_emb[(size_t)t * EMB + e];
}

// ---------------- layernorm (tf32-rounded output: feeds GEMMs only) ----------------
__global__ void ln_kernel(const float* __restrict__ in,
                          const float* __restrict__ gamma,
                          const float* __restrict__ beta,
                          float* __restrict__ out) {
    int row = blockIdx.x;
    int tid = threadIdx.x;                 // 256 threads
    const float* p = in + (size_t)row * EMB;
    float s = 0.f, s2 = 0.f;
    #pragma unroll
    for (int i = 0; i < 4; i++) {
        float v = p[tid + i * 256];
        s += v; s2 += v * v;
    }
    __shared__ float rs[256], rs2[256];
    rs[tid] = s; rs2[tid] = s2;
    __syncthreads();
    for (int st = 128; st > 0; st >>= 1) {
        if (tid < st) { rs[tid] += rs[tid + st]; rs2[tid] += rs2[tid + st]; }
        __syncthreads();
    }
    float mu  = rs[0]  * (1.0f / EMB);
    float var = rs2[0] * (1.0f / EMB) - mu * mu;
    float inv = rsqrtf(var + LN_EPS);
    float* o = out + (size_t)row * EMB;
    #pragma unroll
    for (int i = 0; i < 4; i++) {
        int e = tid + i * 256;
        o[e] = tf32r((p[e] - mu) * inv * gamma[e] + beta[e]);
    }
}

// ---------------- TF32 tensor-core GEMM v3 ----------------
// 128x128x32 CTA tile, 4 warps (128 thr), warp tile 64x64 (LDS/MMA = 1.0),
// cp.async double-buffered. Inputs pre-rounded to tf32.
#define TBM 128
#define TBN 128
#define TBK 32
#define ASTRIDE 36
#define BSTRIDE 136
#define ASZ (TBM * ASTRIDE)
#define BSZ (TBK * BSTRIDE)
#define GEMM_SMEM ((2 * (ASZ + BSZ)) * 4)

__global__ __launch_bounds__(128, 2)
void tgemm3(const float* __restrict__ A, const float* __restrict__ B,
            const float* __restrict__ bias, const float* __restrict__ res,
            float* __restrict__ C, int M, int N, int K, int relu, int out_cvt) {
    extern __shared__ unsigned int smem[];
    unsigned int* As = smem;                 // 2 stages
    unsigned int* Bs = smem + 2 * ASZ;       // 2 stages

    const int tid  = threadIdx.x;
    const int lane = tid & 31;
    const int wid  = tid >> 5;               // 0..3
    const int wm   = (wid >> 1) * 64;        // 2x2 warp grid
    const int wn   = (wid & 1) * 64;
    const int g    = lane >> 2;              // 0..7
    const int tg   = lane & 3;               // 0..3

    const int brow = blockIdx.y * TBM;
    const int bcol = blockIdx.x * TBN;

    const float* Ab = A + (size_t)brow * K;
    const float* Bb = B + bcol;

    // cp.async index mapping (128 threads, float4 granularity)
    const int arow = tid >> 3;              // 0..15 (+ i*16), col (tid&7)*4
    const int acg  = (tid & 7) * 4;
    const int brw  = tid >> 5;              // 0..3 (+ i*4), col (tid&31)*4
    const int bcg  = (tid & 31) * 4;

    const unsigned int sA = (unsigned int)__cvta_generic_to_shared(As);
    const unsigned int sB = (unsigned int)__cvta_generic_to_shared(Bs);

    float acc[4][8][4];
    #pragma unroll
    for (int i = 0; i < 4; i++)
        #pragma unroll
        for (int j = 0; j < 8; j++)
            #pragma unroll
            for (int c = 0; c < 4; c++) acc[i][j][c] = 0.f;

    const int KT = K / TBK;

    #define LOAD_STAGE(stg, kt_)                                              \
    do {                                                                      \
        int k0 = (kt_) * TBK;                                                 \
        _Pragma("unroll")                                                     \
        for (int i = 0; i < 8; i++) {                                         \
            int r = arow + i * 16;                                            \
            CP_ASYNC16(sA + ((stg) * ASZ + r * ASTRIDE + acg) * 4,            \
                       Ab + (size_t)r * K + k0 + acg);                        \
        }                                                                     \
        _Pragma("unroll")                                                     \
        for (int i = 0; i < 8; i++) {                                         \
            int r = brw + i * 4;                                              \
            CP_ASYNC16(sB + ((stg) * BSZ + r * BSTRIDE + bcg) * 4,            \
                       Bb + (size_t)(k0 + r) * N + bcg);                      \
        }                                                                     \
        CP_COMMIT();                                                          \
    } while (0)

    LOAD_STAGE(0, 0);

    for (int kt = 0; kt < KT; kt++) {
        const int cur = kt & 1;
        if (kt + 1 < KT) {
            LOAD_STAGE(cur ^ 1, kt + 1);
            CP_WAIT(1);
        } else {
            CP_WAIT(0);
        }
        __syncthreads();

        const unsigned int* Ac = As + cur * ASZ;
        const unsigned int* Bc = Bs + cur * BSZ;
        #pragma unroll
        for (int ks = 0; ks < 4; ks++) {
            const int k = ks * 8 + tg;
            unsigned int af[4][4], bf[8][2];
            #pragma unroll
            for (int mt = 0; mt < 4; mt++) {
                int r = wm + mt * 16 + g;
                af[mt][0] = Ac[r * ASTRIDE + k];
                af[mt][1] = Ac[(r + 8) * ASTRIDE + k];
                af[mt][2] = Ac[r * ASTRIDE + k + 4];
                af[mt][3] = Ac[(r + 8) * ASTRIDE + k + 4];
            }
            #pragma unroll
            for (int nt = 0; nt < 8; nt++) {
                int c = wn + nt * 8 + g;
                bf[nt][0] = Bc[k * BSTRIDE + c];
                bf[nt][1] = Bc[(k + 4) * BSTRIDE + c];
            }
            #pragma unroll
            for (int mt = 0; mt < 4; mt++)
                #pragma unroll
                for (int nt = 0; nt < 8; nt++)
                    MMA_TF32(acc[mt][nt], af[mt], bf[nt]);
        }
        __syncthreads();
    }

    // epilogue
    #pragma unroll
    for (int mt = 0; mt < 4; mt++) {
        int r0 = brow + wm + mt * 16 + g;
        #pragma unroll
        for (int nt = 0; nt < 8; nt++) {
            int c0 = bcol + wn + nt * 8 + tg * 2;
            float b0 = 0.f, b1 = 0.f;
            if (bias) { b0 = bias[c0]; b1 = bias[c0 + 1]; }
            #pragma unroll
            for (int half = 0; half < 2; half++) {
                int r = r0 + half * 8;
                float v0 = acc[mt][nt][half * 2 + 0] + b0;
                float v1 = acc[mt][nt][half * 2 + 1] + b1;
                if (res) {
                    const float2 rr = *(const float2*)(res + (size_t)r * N + c0);
                    v0 += rr.x; v1 += rr.y;
                }
                if (relu) { v0 = fmaxf(v0, 0.f); v1 = fmaxf(v1, 0.f); }
                if (out_cvt) { v0 = tf32r(v0); v1 = tf32r(v1); }
                float2 o; o.x = v0; o.y = v1;
                *(float2*)(C + (size_t)r * N + c0) = o;
            }
        }
    }
}

// ---------------- flash attention ----------------
#define KPAD 68
#define ATTN_SMEM ((64 * 64 + 3 * 64 * KPAD) * 4)

__global__ __launch_bounds__(256)
void flash_attn(const float* __restrict__ qkv, float* __restrict__ att) {
    extern __shared__ float sm[];
    float* Qs = sm;                       // 64 x 64
    float* Ks = sm + 64 * 64;             // 64 x KPAD
    float* Vs = Ks + 64 * KPAD;           // 64 x KPAD
    float* Ps = Vs + 64 * KPAD;           // 64 x KPAD

    const int qt  = blockIdx.x;
    const int h   = blockIdx.y;
    const int b   = blockIdx.z;
    const int tid = threadIdx.x;
    const int ty  = tid >> 4;             // 0..15 (4 rows each)
    const int tx  = tid & 15;             // cols: tx + 16j

    #pragma unroll
    for (int i = 0; i < 4; i++) {
        int idx = tid + i * 256;
        int r = idx >> 4, c4 = (idx & 15) * 4;
        *(float4*)(Qs + r * 64 + c4) =
            *(const float4*)(qkv + (size_t)(b * SEQ_T + qt * 64 + r) * E3 +
                             h * HEAD_DIM + c4);
    }

    float m[4], l[4], O[4][4];
    #pragma unroll
    for (int i = 0; i < 4; i++) {
        m[i] = -1e30f; l[i] = 0.f;
        #pragma unroll
        for (int j = 0; j < 4; j++) O[i][j] = 0.f;
    }

    for (int kt = 0; kt <= qt; kt++) {
        #pragma unroll
        for (int i = 0; i < 4; i++) {
            int idx = tid + i * 256;
            int r = idx >> 4, c4 = (idx & 15) * 4;
            size_t base = (size_t)(b * SEQ_T + kt * 64 + r) * E3 + h * HEAD_DIM + c4;
            *(float4*)(Ks + r * KPAD + c4) = *(const float4*)(qkv + base + EMB);
            *(float4*)(Vs + r * KPAD + c4) = *(const float4*)(qkv + base + 2 * EMB);
        }
        __syncthreads();

        float s[4][4];
        #pragma unroll
        for (int i = 0; i < 4; i++)
            #pragma unroll
            for (int j = 0; j < 4; j++) s[i][j] = 0.f;
        #pragma unroll
        for (int d4 = 0; d4 < 16; d4++) {
            float4 q[4];
            #pragma unroll
            for (int i = 0; i < 4; i++)
                q[i] = *(const float4*)(Qs + (ty * 4 + i) * 64 + d4 * 4);
            #pragma unroll
            for (int j = 0; j < 4; j++) {
                float4 k = *(const float4*)(Ks + (tx + 16 * j) * KPAD + d4 * 4);
                #pragma unroll
                for (int i = 0; i < 4; i++)
                    s[i][j] += q[i].x * k.x + q[i].y * k.y + q[i].z * k.z + q[i].w * k.w;
            }
        }

        #pragma unroll
        for (int i = 0; i < 4; i++) {
            int grow = qt * 64 + ty * 4 + i;
            float mloc = -1e30f;
            #pragma unroll
            for (int j = 0; j < 4; j++) {
                int gcol = kt * 64 + tx + 16 * j;
                float sv = s[i][j] * ATT_SCALE;
                if (gcol > grow) sv = -1e30f;
                s[i][j] = sv;
                mloc = fmaxf(mloc, sv);
            }
            #pragma unroll
            for (int off = 8; off > 0; off >>= 1)
                mloc = fmaxf(mloc, __shfl_xor_sync(0xffffffffu, mloc, off, 16));
            float mnew = fmaxf(m[i], mloc);
            float corr = __expf(m[i] - mnew);
            float rs = 0.f;
            #pragma unroll
            for (int j = 0; j < 4; j++) {
                float p = __expf(s[i][j] - mnew);
                s[i][j] = p; rs += p;
            }
            #pragma unroll
            for (int off = 8; off > 0; off >>= 1)
                rs += __shfl_xor_sync(0xffffffffu, rs, off, 16);
            l[i] = l[i] * corr + rs;
            m[i] = mnew;
            #pragma unroll
            for (int j = 0; j < 4; j++) {
                O[i][j] *= corr;
                Ps[(ty * 4 + i) * KPAD + tx + 16 * j] = s[i][j];
            }
        }
        __syncthreads();

        #pragma unroll 4
        for (int c = 0; c < 64; c++) {
            float p[4], v[4];
            #pragma unroll
            for (int i = 0; i < 4; i++) p[i] = Ps[(ty * 4 + i) * KPAD + c];
            #pragma unroll
            for (int j = 0; j < 4; j++) v[j] = Vs[c * KPAD + tx + 16 * j];
            #pragma unroll
            for (int i = 0; i < 4; i++)
                #pragma unroll
                for (int j = 0; j < 4; j++)
                    O[i][j] += p[i] * v[j];
        }
        __syncthreads();
    }

    #pragma unroll
    for (int i = 0; i < 4; i++) {
        float inv = 1.0f / l[i];
        size_t rbase = (size_t)(b * SEQ_T + qt * 64 + ty * 4 + i) * EMB + h * HEAD_DIM;
        #pragma unroll
        for (int j = 0; j < 4; j++)
            att[rbase + tx + 16 * j] = tf32r(O[i][j] * inv);
    }
}

// ---------------- loss ----------------
__global__ __launch_bounds__(256)
void loss_rows_kernel(const float* __restrict__ logits, const int* __restrict__ tgt) {
    int row = blockIdx.x;
    int tid = threadIdx.x;
    const float* lp = logits + (size_t)row * VOCAB;
    __shared__ float red[256];
    float m = -1e30f;
    for (int i = tid; i < VOCAB; i += 256) m = fmaxf(m, lp[i]);
    red[tid] = m; __syncthreads();
    for (int st = 128; st > 0; st >>= 1) {
        if (tid < st) red[tid] = fmaxf(red[tid], red[tid + st]);
        __syncthreads();
    }
    m = red[0]; __syncthreads();
    float s = 0.f;
    for (int i = tid; i < VOCAB; i += 256) s += __expf(lp[i] - m);
    red[tid] = s; __syncthreads();
    for (int st = 128; st > 0; st >>= 1) {
        if (tid < st) red[tid] += red[tid + st];
        __syncthreads();
    }
    if (tid == 0)
        g_rowloss[row] = -(lp[tgt[row]] - m - logf(red[0]));
}

__global__ __launch_bounds__(256)
void loss_final_kernel(float* __restrict__ out_loss) {
    int tid = threadIdx.x;
    __shared__ float red[256];
    float s = 0.f;
    #pragma unroll
    for (int i = 0; i < ROWS / 256; i++) s += g_rowloss[tid + i * 256];
    red[tid] = s; __syncthreads();
    for (int st = 128; st > 0; st >>= 1) {
        if (tid < st) red[tid] += red[tid + st];
        __syncthreads();
    }
    if (tid == 0) out_loss[0] = red[0] * (1.0f / ROWS);
}

// ---------------- launch ----------------
static void run_gemm(const float* A, const float* B, const float* bias,
                     const float* res, float* C, int M, int N, int K,
                     int relu, int out_cvt) {
    dim3 grid(N / TBN, M / TBM);
    tgemm3<<<grid, 128, GEMM_SMEM>>>(A, B, bias, res, C, M, N, K, relu, out_cvt);
}

extern "C" void kernel_launch(void* const* d_in, const int* in_sizes, int n_in,
                              void* d_out, int out_size) {
    const int*   ids     = (const int*)  d_in[0];
    const int*   targets = (const int*)  d_in[1];
    const float* tok_emb = (const float*)d_in[2];
    const float* pos_emb = (const float*)d_in[3];
    const float* wq      = (const float*)d_in[4];
    const float* wk      = (const float*)d_in[5];
    const float* wv      = (const float*)d_in[6];
    const float* wo      = (const float*)d_in[7];
    const float* bo      = (const float*)d_in[8];
    const float* ln1_g   = (const float*)d_in[9];
    const float* ln1_b   = (const float*)d_in[10];
    const float* w1      = (const float*)d_in[11];
    const float* b1      = (const float*)d_in[12];
    const float* w2      = (const float*)d_in[13];
    const float* b2      = (const float*)d_in[14];
    const float* lnf_g   = (const float*)d_in[15];
    const float* lnf_b   = (const float*)d_in[16];
    const float* lm_w    = (const float*)d_in[17];
    const float* lm_b    = (const float*)d_in[18];

    static int attr_set = 0;
    if (!attr_set) {
        cudaFuncSetAttribute(tgemm3, cudaFuncAttributeMaxDynamicSharedMemorySize,
                             GEMM_SMEM);
        cudaFuncSetAttribute(flash_attn, cudaFuncAttributeMaxDynamicSharedMemorySize,
                             ATTN_SMEM);
        attr_set = 1;
    }

    float* x;   cudaGetSymbolAddress((void**)&x,   g_x);
    float* h;   cudaGetSymbolAddress((void**)&h,   g_h);
    float* qkv; cudaGetSymbolAddress((void**)&qkv, g_qkv);
    float* att; cudaGetSymbolAddress((void**)&att, g_att);
    float* ff;  cudaGetSymbolAddress((void**)&ff,  g_ff);
    float* wqkvp; cudaGetSymbolAddress((void**)&wqkvp, g_wqkv);
    float* wop;   cudaGetSymbolAddress((void**)&wop,   g_wo);
    float* w1p;   cudaGetSymbolAddress((void**)&w1p,   g_w1);
    float* w2p;   cudaGetSymbolAddress((void**)&w2p,   g_w2);
    float* lmwp;  cudaGetSymbolAddress((void**)&lmwp,  g_lmw);
    float* glog;  cudaGetSymbolAddress((void**)&glog,  g_logits);

    const long long NLOG = (long long)ROWS * VOCAB;
    float* logits = ((long long)out_size >= NLOG) ? (float*)d_out : glog;

    // weight prep (tf32 rounding once per launch)
    {
        int total = NL_LAYERS * EMB * E3;
        prepack_qkv<<<(total + 255) / 256, 256>>>(wq, wk, wv);
        int n4;
        n4 = NL_LAYERS * EMB * EMB / 4;
        cvt_kernel<<<(n4 + 255) / 256, 256>>>(wo, wop, n4);
        n4 = NL_LAYERS * EMB * FF_DIM / 4;
        cvt_kernel<<<(n4 + 255) / 256, 256>>>(w1, w1p, n4);
        cvt_kernel<<<(n4 + 255) / 256, 256>>>(w2, w2p, n4);
        n4 = EMB * VOCAB / 4;
        cvt_kernel<<<(n4 + 255) / 256, 256>>>(lm_w, lmwp, n4);
    }

    // embedding
    embed_kernel<<<(ROWS * EMB + 255) / 256, 256>>>(ids, tok_emb, pos_emb);

    dim3 agrid(SEQ_T / 64, N_HEADS, BATCH);
    for (int l = 0; l < NL_LAYERS; l++) {
        const float* g1  = ln1_g + l * EMB;
        const float* bt1 = ln1_b + l * EMB;
        ln_kernel<<<ROWS, 256>>>(x, g1, bt1, h);
        run_gemm(h, wqkvp + (size_t)l * EMB * E3, nullptr, nullptr, qkv,
                 ROWS, E3, EMB, 0, 0);
        flash_attn<<<agrid, 256, ATTN_SMEM>>>(qkv, att);
        run_gemm(att, wop + (size_t)l * EMB * EMB, bo + l * EMB, x, x,
                 ROWS, EMB, EMB, 0, 0);
        ln_kernel<<<ROWS, 256>>>(x, g1, bt1, h);
        run_gemm(h, w1p + (size_t)l * EMB * FF_DIM, b1 + l * FF_DIM, nullptr, ff,
                 ROWS, FF_DIM, EMB, 1, 1);
        run_gemm(ff, w2p + (size_t)l * FF_DIM * EMB, b2 + l * EMB, x, x,
                 ROWS, EMB, FF_DIM, 0, 0);
    }

    ln_kernel<<<ROWS, 256>>>(x, lnf_g, lnf_b, h);
    run_gemm(h, lmwp, lm_b, nullptr, logits, ROWS, VOCAB, EMB, 0, 0);

    if (out_size == 1 || (long long)out_size > NLOG) {
        loss_rows_kernel<<<ROWS, 256>>>(logits, targets);
        float* loss_dst = (out_size == 1) ? (float*)d_out
                                          : ((float*)d_out + NLOG);
        loss_final_kernel<<<1, 256>>>(loss_dst);
    }
}

// round 10
// speedup vs baseline: 1.5464x; 1.5464x over previous
#include <cuda_runtime.h>
#include <cuda_fp16.h>
#include <math.h>
#include <stdint.h>

// ---------------- problem constants ----------------
#define NL_LAYERS 3
#define N_HEADS   16
#define EMB       1024
#define HEAD_DIM  64
#define SEQ_T     1024
#define BATCH     4
#define ROWS      (BATCH * SEQ_T)      // 4096
#define VOCAB     32000
#define E3        (3 * EMB)            // 3072
#define FF_DIM    (4 * EMB)            // 4096
#define LN_EPS    1e-5f
#define ATT_SCALE 0.03125f             // 1/sqrt(EMB) = 1/32

// ---------------- scratch (device globals; no allocation allowed) ----------------
__device__ float  g_x   [ROWS * EMB];            // residual (fp32)
__device__ __half g_h16 [ROWS * EMB];            // LN output (fp16, GEMM A)
__device__ float  g_qkv [ROWS * E3];             // qkv activations (fp32)
__device__ __half g_att16[ROWS * EMB];           // attention out (fp16, GEMM A)
__device__ __half g_ff16[ROWS * FF_DIM];         // FFN hidden (fp16, GEMM A)
__device__ __half g_wqkv[NL_LAYERS * E3 * EMB];  // transposed [3E][E] fp16
__device__ __half g_wo  [NL_LAYERS * EMB * EMB]; // transposed fp16
__device__ __half g_w1  [NL_LAYERS * FF_DIM * EMB];
__device__ __half g_w2  [NL_LAYERS * EMB * FF_DIM];
__device__ __half g_lmw [(size_t)VOCAB * EMB];
__device__ float  g_logits[(size_t)ROWS * VOCAB];
__device__ float  g_rowloss[ROWS];

// ---------------- async copy ----------------
#define CP_ASYNC16(dst, src)                                                  \
    asm volatile("cp.async.cg.shared.global [%0], [%1], 16;" ::               \
                 "r"(dst), "l"(src))
#define CP_COMMIT() asm volatile("cp.async.commit_group;")
#define CP_WAIT(n)  asm volatile("cp.async.wait_group %0;" :: "n"(n))

// fp16 mma: D(f32) += A(f16) @ B(f16), m16n8k16, row.col
#define MMA_F16(d, a, b)                                                      \
    asm volatile("mma.sync.aligned.m16n8k16.row.col.f32.f16.f16.f32 "         \
                 "{%0,%1,%2,%3}, {%4,%5,%6,%7}, {%8,%9}, {%0,%1,%2,%3};"      \
                 : "+f"(d[0]), "+f"(d[1]), "+f"(d[2]), "+f"(d[3])             \
                 : "r"(a[0]), "r"(a[1]), "r"(a[2]), "r"(a[3]),                \
                   "r"(b[0]), "r"(b[1]))

// ---------------- prepack wq/wk/wv -> transposed [l][3E][E] fp16 ----------------
__global__ void prepack_qkv(const float* __restrict__ wq,
                            const float* __restrict__ wk,
                            const float* __restrict__ wv) {
    int idx = blockIdx.x * blockDim.x + threadIdx.x;
    int total = NL_LAYERS * E3 * EMB;
    if (idx >= total) return;
    int l = idx / (E3 * EMB);
    int r = idx % (E3 * EMB);
    int c = r / EMB;               // n of 3E
    int e = r % EMB;               // k of E
    float v;
    if (c < EMB) {
        int h = c >> 6, d = c & 63;
        v = wq[(((size_t)l * N_HEADS + h) * EMB + e) * HEAD_DIM + d];
    } else if (c < 2 * EMB) {
        int c2 = c - EMB; int h = c2 >> 6, d = c2 & 63;
        v = wk[(((size_t)l * N_HEADS + h) * EMB + e) * HEAD_DIM + d];
    } else {
        int c2 = c - 2 * EMB; int h = c2 >> 6, d = c2 & 63;
        v = wv[(((size_t)l * N_HEADS + h) * EMB + e) * HEAD_DIM + d];
    }
    g_wqkv[idx] = __float2half(v);
}

// ---------------- tiled transpose + fp16 cvt: src[R][C] f32 -> dst[C][R] f16 ----
__global__ void transpose_cvt(const float* __restrict__ src, __half* __restrict__ dst,
                              int R, int C) {
    __shared__ float tile[32][33];
    int bx = blockIdx.x * 32;   // C offset
    int by = blockIdx.y * 32;   // R offset
    int tx = threadIdx.x, ty = threadIdx.y;   // 32 x 8
    #pragma unroll
    for (int i = 0; i < 32; i += 8)
        tile[ty + i][tx] = src[(size_t)(by + ty + i) * C + bx + tx];
    __syncthreads();
    #pragma unroll
    for (int i = 0; i < 32; i += 8)
        dst[(size_t)(bx + ty + i) * R + by + tx] = __float2half(tile[tx][ty + i]);
}

// ---------------- embedding ----------------
__global__ void embed_kernel(const int* __restrict__ ids,
                             const float* __restrict__ tok_emb,
                             const float* __restrict__ pos_emb) {
    int idx = blockIdx.x * blockDim.x + threadIdx.x;
    if (idx >= ROWS * EMB) return;
    int row = idx >> 10;
    int e   = idx & 1023;
    int t   = row & (SEQ_T - 1);
    int tok = ids[row];
    g_x[idx] = tok_emb[(size_t)tok * EMB + e] + pos_emb[(size_t)t * EMB + e];
}

// ---------------- layernorm (fp16 output: feeds GEMMs) ----------------
__global__ void ln_kernel(const float* __restrict__ in,
                          const float* __restrict__ gamma,
                          const float* __restrict__ beta,
                          __half* __restrict__ out) {
    int row = blockIdx.x;
    int tid = threadIdx.x;                 // 256 threads
    const float* p = in + (size_t)row * EMB;
    float s = 0.f, s2 = 0.f;
    #pragma unroll
    for (int i = 0; i < 4; i++) {
        float v = p[tid + i * 256];
        s += v; s2 += v * v;
    }
    __shared__ float rs[256], rs2[256];
    rs[tid] = s; rs2[tid] = s2;
    __syncthreads();
    for (int st = 128; st > 0; st >>= 1) {
        if (tid < st) { rs[tid] += rs[tid + st]; rs2[tid] += rs2[tid + st]; }
        __syncthreads();
    }
    float mu  = rs[0]  * (1.0f / EMB);
    float var = rs2[0] * (1.0f / EMB) - mu * mu;
    float inv = rsqrtf(var + LN_EPS);
    __half* o = out + (size_t)row * EMB;
    #pragma unroll
    for (int i = 0; i < 4; i++) {
        int e = tid + i * 256;
        o[e] = __float2half((p[e] - mu) * inv * gamma[e] + beta[e]);
    }
}

// ---------------- fp16 tensor-core GEMM ----------------
// C[MxN](f32, opt) / Ch[MxN](f16, opt) = A[MxK]f16 @ Bt[NxK]^T f16 (+bias)(+res)(relu)
// CTA 128x128x64, 8 warps (2m x 4n), warp tile 64x32, mma m16n8k16.
// Shared layout: [row][k] fp16, row stride 72 halves (36 words) -> conflict-free.
#define TBM 128
#define TBN 128
#define TBK 64
#define HSTR 72                          // halves per row (36 words)
#define STG_WORDS (128 * 36)             // words per (A or B) stage
#define GEMM_SMEM (4 * STG_WORDS * 4)    // 2 stages x (A+B) = 73728 B

__global__ __launch_bounds__(256, 2)
void hgemm(const __half* __restrict__ A, const __half* __restrict__ Bt,
           const float* __restrict__ bias, const float* __restrict__ res,
           float* __restrict__ C, __half* __restrict__ Ch,
           int M, int N, int K, int relu) {
    extern __shared__ unsigned int smem[];
    // layout: [stage0 A][stage0 B][stage1 A][stage1 B]
    const int tid  = threadIdx.x;
    const int lane = tid & 31;
    const int wid  = tid >> 5;
    const int wm   = (wid & 1) * 64;
    const int wn   = (wid >> 1) * 32;
    const int g    = lane >> 2;
    const int tg   = lane & 3;

    const int brow = blockIdx.y * TBM;
    const int bcol = blockIdx.x * TBN;

    const __half* Ag = A  + (size_t)brow * K;
    const __half* Bg = Bt + (size_t)bcol * K;

    // load mapping: chunk = tid + i*256; row = chunk>>3 (0..127), jc = chunk&7
    const int lrow = tid >> 3;
    const int ljc  = tid & 7;

    const unsigned sbase = (unsigned)__cvta_generic_to_shared(smem);

    float acc[4][4][4];
    #pragma unroll
    for (int i = 0; i < 4; i++)
        #pragma unroll
        for (int j = 0; j < 4; j++)
            #pragma unroll
            for (int c = 0; c < 4; c++) acc[i][j][c] = 0.f;

    const int KT = K / TBK;

    // one stage: A tile then B tile; bytes: row*144 + jc*16
    #define LOAD_STAGE(stg, kt_) do {                                         \
        int k0 = (kt_) * TBK;                                                 \
        unsigned aB = sbase + (stg) * 2 * STG_WORDS * 4;                      \
        unsigned bB = aB + STG_WORDS * 4;                                     \
        _Pragma("unroll")                                                     \
        for (int i = 0; i < 4; i++) {                                         \
            int r = lrow + i * 32;                                            \
            CP_ASYNC16(aB + r * 144 + ljc * 16,                               \
                       Ag + (size_t)r * K + k0 + ljc * 8);                    \
            CP_ASYNC16(bB + r * 144 + ljc * 16,                               \
                       Bg + (size_t)r * K + k0 + ljc * 8);                    \
        }                                                                     \
        CP_COMMIT();                                                          \
    } while (0)

    LOAD_STAGE(0, 0);

    for (int kt = 0; kt < KT; kt++) {
        const int cur = kt & 1;
        if (kt + 1 < KT) {
            LOAD_STAGE(cur ^ 1, kt + 1);
            CP_WAIT(1);
        } else {
            CP_WAIT(0);
        }
        __syncthreads();

        const unsigned int* Ac = smem + cur * 2 * STG_WORDS;
        const unsigned int* Bc = Ac + STG_WORDS;
        #pragma unroll
        for (int ks = 0; ks < 4; ks++) {
            // word offset of k within row: ks*8 + tg (+4 for +8 halves)
            const int kw = ks * 8 + tg;
            unsigned a_[4][4], b_[4][2];
            #pragma unroll
            for (int mt = 0; mt < 4; mt++) {
                int r = wm + mt * 16 + g;
                a_[mt][0] = Ac[r * 36 + kw];
                a_[mt][1] = Ac[(r + 8) * 36 + kw];
                a_[mt][2] = Ac[r * 36 + kw + 4];
                a_[mt][3] = Ac[(r + 8) * 36 + kw + 4];
            }
            #pragma unroll
            for (int nt = 0; nt < 4; nt++) {
                int n = wn + nt * 8 + g;
                b_[nt][0] = Bc[n * 36 + kw];
                b_[nt][1] = Bc[n * 36 + kw + 4];
            }
            #pragma unroll
            for (int mt = 0; mt < 4; mt++)
                #pragma unroll
                for (int nt = 0; nt < 4; nt++)
                    MMA_F16(acc[mt][nt], a_[mt], b_[nt]);
        }
        __syncthreads();
    }

    // epilogue
    #pragma unroll
    for (int mt = 0; mt < 4; mt++) {
        int r0 = brow + wm + mt * 16 + g;
        #pragma unroll
        for (int nt = 0; nt < 4; nt++) {
            int c0 = bcol + wn + nt * 8 + tg * 2;
            float b0 = 0.f, b1 = 0.f;
            if (bias) { b0 = bias[c0]; b1 = bias[c0 + 1]; }
            #pragma unroll
            for (int half_ = 0; half_ < 2; half_++) {
                int r = r0 + half_ * 8;
                float v0 = acc[mt][nt][half_ * 2 + 0] + b0;
                float v1 = acc[mt][nt][half_ * 2 + 1] + b1;
                if (res) {
                    const float2 rr = *(const float2*)(res + (size_t)r * N + c0);
                    v0 += rr.x; v1 += rr.y;
                }
                if (relu) { v0 = fmaxf(v0, 0.f); v1 = fmaxf(v1, 0.f); }
                if (C) {
                    float2 o; o.x = v0; o.y = v1;
                    *(float2*)(C + (size_t)r * N + c0) = o;
                }
                if (Ch) {
                    __half2 oh = __floats2half2_rn(v0, v1);
                    *(__half2*)(Ch + (size_t)r * N + c0) = oh;
                }
            }
        }
    }
}

// ---------------- flash attention (fp32 compute, fp16 output) ----------------
#define KPAD 68
#define ATTN_SMEM ((64 * 64 + 3 * 64 * KPAD) * 4)

__global__ __launch_bounds__(256)
void flash_attn(const float* __restrict__ qkv, __half* __restrict__ att) {
    extern __shared__ float sm[];
    float* Qs = sm;
    float* Ks = sm + 64 * 64;
    float* Vs = Ks + 64 * KPAD;
    float* Ps = Vs + 64 * KPAD;

    const int qt  = blockIdx.x;
    const int h   = blockIdx.y;
    const int b   = blockIdx.z;
    const int tid = threadIdx.x;
    const int ty  = tid >> 4;
    const int tx  = tid & 15;

    #pragma unroll
    for (int i = 0; i < 4; i++) {
        int idx = tid + i * 256;
        int r = idx >> 4, c4 = (idx & 15) * 4;
        *(float4*)(Qs + r * 64 + c4) =
            *(const float4*)(qkv + (size_t)(b * SEQ_T + qt * 64 + r) * E3 +
                             h * HEAD_DIM + c4);
    }

    float m[4], l[4], O[4][4];
    #pragma unroll
    for (int i = 0; i < 4; i++) {
        m[i] = -1e30f; l[i] = 0.f;
        #pragma unroll
        for (int j = 0; j < 4; j++) O[i][j] = 0.f;
    }

    for (int kt = 0; kt <= qt; kt++) {
        #pragma unroll
        for (int i = 0; i < 4; i++) {
            int idx = tid + i * 256;
            int r = idx >> 4, c4 = (idx & 15) * 4;
            size_t base = (size_t)(b * SEQ_T + kt * 64 + r) * E3 + h * HEAD_DIM + c4;
            *(float4*)(Ks + r * KPAD + c4) = *(const float4*)(qkv + base + EMB);
            *(float4*)(Vs + r * KPAD + c4) = *(const float4*)(qkv + base + 2 * EMB);
        }
        __syncthreads();

        float s[4][4];
        #pragma unroll
        for (int i = 0; i < 4; i++)
            #pragma unroll
            for (int j = 0; j < 4; j++) s[i][j] = 0.f;
        #pragma unroll
        for (int d4 = 0; d4 < 16; d4++) {
            float4 q[4];
            #pragma unroll
            for (int i = 0; i < 4; i++)
                q[i] = *(const float4*)(Qs + (ty * 4 + i) * 64 + d4 * 4);
            #pragma unroll
            for (int j = 0; j < 4; j++) {
                float4 k = *(const float4*)(Ks + (tx + 16 * j) * KPAD + d4 * 4);
                #pragma unroll
                for (int i = 0; i < 4; i++)
                    s[i][j] += q[i].x * k.x + q[i].y * k.y + q[i].z * k.z + q[i].w * k.w;
            }
        }

        #pragma unroll
        for (int i = 0; i < 4; i++) {
            int grow = qt * 64 + ty * 4 + i;
            float mloc = -1e30f;
            #pragma unroll
            for (int j = 0; j < 4; j++) {
                int gcol = kt * 64 + tx + 16 * j;
                float sv = s[i][j] * ATT_SCALE;
                if (gcol > grow) sv = -1e30f;
                s[i][j] = sv;
                mloc = fmaxf(mloc, sv);
            }
            #pragma unroll
            for (int off = 8; off > 0; off >>= 1)
                mloc = fmaxf(mloc, __shfl_xor_sync(0xffffffffu, mloc, off, 16));
            float mnew = fmaxf(m[i], mloc);
            float corr = __expf(m[i] - mnew);
            float rs = 0.f;
            #pragma unroll
            for (int j = 0; j < 4; j++) {
                float p = __expf(s[i][j] - mnew);
                s[i][j] = p; rs += p;
            }
            #pragma unroll
            for (int off = 8; off > 0; off >>= 1)
                rs += __shfl_xor_sync(0xffffffffu, rs, off, 16);
            l[i] = l[i] * corr + rs;
            m[i] = mnew;
            #pragma unroll
            for (int j = 0; j < 4; j++) {
                O[i][j] *= corr;
                Ps[(ty * 4 + i) * KPAD + tx + 16 * j] = s[i][j];
            }
        }
        __syncthreads();

        #pragma unroll 4
        for (int c = 0; c < 64; c++) {
            float p[4], v[4];
            #pragma unroll
            for (int i = 0; i < 4; i++) p[i] = Ps[(ty * 4 + i) * KPAD + c];
            #pragma unroll
            for (int j = 0; j < 4; j++) v[j] = Vs[c * KPAD + tx + 16 * j];
            #pragma unroll
            for (int i = 0; i < 4; i++)
                #pragma unroll
                for (int j = 0; j < 4; j++)
                    O[i][j] += p[i] * v[j];
        }
        __syncthreads();
    }

    #pragma unroll
    for (int i = 0; i < 4; i++) {
        float inv = 1.0f / l[i];
        size_t rbase = (size_t)(b * SEQ_T + qt * 64 + ty * 4 + i) * EMB + h * HEAD_DIM;
        #pragma unroll
        for (int j = 0; j < 4; j++)
            att[rbase + tx + 16 * j] = __float2half(O[i][j] * inv);
    }
}

// ---------------- loss ----------------
__global__ __launch_bounds__(256)
void loss_rows_kernel(const float* __restrict__ logits, const int* __restrict__ tgt) {
    int row = blockIdx.x;
    int tid = threadIdx.x;
    const float* lp = logits + (size_t)row * VOCAB;
    __shared__ float red[256];
    float m = -1e30f;
    for (int i = tid; i < VOCAB; i += 256) m = fmaxf(m, lp[i]);
    red[tid] = m; __syncthreads();
    for (int st = 128; st > 0; st >>= 1) {
        if (tid < st) red[tid] = fmaxf(red[tid], red[tid + st]);
        __syncthreads();
    }
    m = red[0]; __syncthreads();
    float s = 0.f;
    for (int i = tid; i < VOCAB; i += 256) s += __expf(lp[i] - m);
    red[tid] = s; __syncthreads();
    for (int st = 128; st > 0; st >>= 1) {
        if (tid < st) red[tid] += red[tid + st];
        __syncthreads();
    }
    if (tid == 0)
        g_rowloss[row] = -(lp[tgt[row]] - m - logf(red[0]));
}

__global__ __launch_bounds__(256)
void loss_final_kernel(float* __restrict__ out_loss) {
    int tid = threadIdx.x;
    __shared__ float red[256];
    float s = 0.f;
    #pragma unroll
    for (int i = 0; i < ROWS / 256; i++) s += g_rowloss[tid + i * 256];
    red[tid] = s; __syncthreads();
    for (int st = 128; st > 0; st >>= 1) {
        if (tid < st) red[tid] += red[tid + st];
        __syncthreads();
    }
    if (tid == 0) out_loss[0] = red[0] * (1.0f / ROWS);
}

// ---------------- launch ----------------
static void run_gemm(const __half* A, const __half* Bt, const float* bias,
                     const float* res, float* C, __half* Ch,
                     int M, int N, int K, int relu) {
    dim3 grid(N / TBN, M / TBM);
    hgemm<<<grid, 256, GEMM_SMEM>>>(A, Bt, bias, res, C, Ch, M, N, K, relu);
}

extern "C" void kernel_launch(void* const* d_in, const int* in_sizes, int n_in,
                              void* d_out, int out_size) {
    const int*   ids     = (const int*)  d_in[0];
    const int*   targets = (const int*)  d_in[1];
    const float* tok_emb = (const float*)d_in[2];
    const float* pos_emb = (const float*)d_in[3];
    const float* wq      = (const float*)d_in[4];
    const float* wk      = (const float*)d_in[5];
    const float* wv      = (const float*)d_in[6];
    const float* wo      = (const float*)d_in[7];
    const float* bo      = (const float*)d_in[8];
    const float* ln1_g   = (const float*)d_in[9];
    const float* ln1_b   = (const float*)d_in[10];
    const float* w1      = (const float*)d_in[11];
    const float* b1      = (const float*)d_in[12];
    const float* w2      = (const float*)d_in[13];
    const float* b2      = (const float*)d_in[14];
    const float* lnf_g   = (const float*)d_in[15];
    const float* lnf_b   = (const float*)d_in[16];
    const float* lm_w    = (const float*)d_in[17];
    const float* lm_b    = (const float*)d_in[18];

    static int attr_set = 0;
    if (!attr_set) {
        cudaFuncSetAttribute(hgemm, cudaFuncAttributeMaxDynamicSharedMemorySize,
                             GEMM_SMEM);
        cudaFuncSetAttribute(flash_attn, cudaFuncAttributeMaxDynamicSharedMemorySize,
                             ATTN_SMEM);
        attr_set = 1;
    }

    float*  x;    cudaGetSymbolAddress((void**)&x,    g_x);
    __half* h16;  cudaGetSymbolAddress((void**)&h16,  g_h16);
    float*  qkv;  cudaGetSymbolAddress((void**)&qkv,  g_qkv);
    __half* att16;cudaGetSymbolAddress((void**)&att16,g_att16);
    __half* ff16; cudaGetSymbolAddress((void**)&ff16, g_ff16);
    __half* wqkvp;cudaGetSymbolAddress((void**)&wqkvp,g_wqkv);
    __half* wop;  cudaGetSymbolAddress((void**)&wop,  g_wo);
    __half* w1p;  cudaGetSymbolAddress((void**)&w1p,  g_w1);
    __half* w2p;  cudaGetSymbolAddress((void**)&w2p,  g_w2);
    __half* lmwp; cudaGetSymbolAddress((void**)&lmwp, g_lmw);
    float*  glog; cudaGetSymbolAddress((void**)&glog, g_logits);

    const long long NLOG = (long long)ROWS * VOCAB;
    float* logits = ((long long)out_size >= NLOG) ? (float*)d_out : glog;

    // weight prep: transpose + fp16 cvt (per launch, deterministic)
    {
        int total = NL_LAYERS * E3 * EMB;
        prepack_qkv<<<(total + 255) / 256, 256>>>(wq, wk, wv);
        dim3 tb(32, 8);
        for (int l = 0; l < NL_LAYERS; l++) {
            transpose_cvt<<<dim3(EMB / 32, EMB / 32), tb>>>(
                wo + (size_t)l * EMB * EMB, wop + (size_t)l * EMB * EMB, EMB, EMB);
            transpose_cvt<<<dim3(FF_DIM / 32, EMB / 32), tb>>>(
                w1 + (size_t)l * EMB * FF_DIM, w1p + (size_t)l * EMB * FF_DIM,
                EMB, FF_DIM);
            transpose_cvt<<<dim3(EMB / 32, FF_DIM / 32), tb>>>(
                w2 + (size_t)l * FF_DIM * EMB, w2p + (size_t)l * FF_DIM * EMB,
                FF_DIM, EMB);
        }
        transpose_cvt<<<dim3(VOCAB / 32, EMB / 32), tb>>>(lm_w, lmwp, EMB, VOCAB);
    }

    // embedding
    embed_kernel<<<(ROWS * EMB + 255) / 256, 256>>>(ids, tok_emb, pos_emb);

    dim3 agrid(SEQ_T / 64, N_HEADS, BATCH);
    for (int l = 0; l < NL_LAYERS; l++) {
        const float* g1  = ln1_g + l * EMB;
        const float* bt1 = ln1_b + l * EMB;
        // h16 = f16(LN(x))
        ln_kernel<<<ROWS, 256>>>(x, g1, bt1, h16);
        // qkv = h @ Wqkv^T   (fp32 out, feeds attention)
        run_gemm(h16, wqkvp + (size_t)l * E3 * EMB, nullptr, nullptr, qkv, nullptr,
                 ROWS, E3, EMB, 0);
        // flash attention -> att16
        flash_attn<<<agrid, 256, ATTN_SMEM>>>(qkv, att16);
        // x = x + att @ wo + bo
        run_gemm(att16, wop + (size_t)l * EMB * EMB, bo + l * EMB, x, x, nullptr,
                 ROWS, EMB, EMB, 0);
        // h16 = f16(LN(x))
        ln_kernel<<<ROWS, 256>>>(x, g1, bt1, h16);
        // ff16 = f16(relu(h @ w1 + b1))   (fp16-only output)
        run_gemm(h16, w1p + (size_t)l * EMB * FF_DIM, b1 + l * FF_DIM, nullptr,
                 nullptr, ff16, ROWS, FF_DIM, EMB, 1);
        // x = x + ff @ w2 + b2
        run_gemm(ff16, w2p + (size_t)l * FF_DIM * EMB, b2 + l * EMB, x, x, nullptr,
                 ROWS, EMB, FF_DIM, 0);
    }

    // final LN + lm head
    ln_kernel<<<ROWS, 256>>>(x, lnf_g, lnf_b, h16);
    run_gemm(h16, lmwp, lm_b, nullptr, logits, nullptr, ROWS, VOCAB, EMB, 0);

    // loss (deterministic two-stage reduction)
    if (out_size == 1 || (long long)out_size > NLOG) {
        loss_rows_kernel<<<ROWS, 256>>>(logits, targets);
        float* loss_dst = (out_size == 1) ? (float*)d_out
                                          : ((float*)d_out + NLOG);
        loss_final_kernel<<<1, 256>>>(loss_dst);
    }
}

// round 11
// speedup vs baseline: 1.7640x; 1.1408x over previous
#include <cuda_runtime.h>
#include <cuda_fp16.h>
#include <math.h>
#include <stdint.h>

// ---------------- problem constants ----------------
#define NL_LAYERS 3
#define N_HEADS   16
#define EMB       1024
#define HEAD_DIM  64
#define SEQ_T     1024
#define BATCH     4
#define ROWS      (BATCH * SEQ_T)      // 4096
#define VOCAB     32000
#define E3        (3 * EMB)            // 3072
#define FF_DIM    (4 * EMB)            // 4096
#define LN_EPS    1e-5f
#define ATT_SCALE 0.03125f             // 1/sqrt(EMB) = 1/32

// ---------------- scratch (device globals; no allocation allowed) ----------------
__device__ float  g_x   [ROWS * EMB];            // residual (fp32)
__device__ __half g_h16 [ROWS * EMB];            // LN output (fp16, GEMM A)
__device__ float  g_qkv [ROWS * E3];             // qkv activations (fp32)
__device__ __half g_att16[ROWS * EMB];           // attention out (fp16, GEMM A)
__device__ __half g_ff16[ROWS * FF_DIM];         // FFN hidden (fp16, GEMM A)
__device__ __half g_wqkv[NL_LAYERS * E3 * EMB];  // transposed [3E][E] fp16
__device__ __half g_wo  [NL_LAYERS * EMB * EMB]; // transposed fp16
__device__ __half g_w1  [NL_LAYERS * FF_DIM * EMB];
__device__ __half g_w2  [NL_LAYERS * EMB * FF_DIM];
__device__ __half g_lmw [(size_t)VOCAB * EMB];
__device__ float  g_logits[(size_t)ROWS * VOCAB];
__device__ float  g_rowloss[ROWS];

// ---------------- async copy ----------------
#define CP_ASYNC16(dst, src)                                                  \
    asm volatile("cp.async.cg.shared.global [%0], [%1], 16;" ::               \
                 "r"(dst), "l"(src))
#define CP_COMMIT() asm volatile("cp.async.commit_group;")
#define CP_WAIT(n)  asm volatile("cp.async.wait_group %0;" :: "n"(n))

// fp16 mma: D(f32) += A(f16) @ B(f16), m16n8k16, row.col
#define MMA_F16(d, a, b)                                                      \
    asm volatile("mma.sync.aligned.m16n8k16.row.col.f32.f16.f16.f32 "         \
                 "{%0,%1,%2,%3}, {%4,%5,%6,%7}, {%8,%9}, {%0,%1,%2,%3};"      \
                 : "+f"(d[0]), "+f"(d[1]), "+f"(d[2]), "+f"(d[3])             \
                 : "r"(a[0]), "r"(a[1]), "r"(a[2]), "r"(a[3]),                \
                   "r"(b[0]), "r"(b[1]))

#define LDSM_X4(r0, r1, r2, r3, addr)                                         \
    asm volatile("ldmatrix.sync.aligned.m8n8.x4.shared.b16 {%0,%1,%2,%3}, [%4];" \
                 : "=r"(r0), "=r"(r1), "=r"(r2), "=r"(r3) : "r"(addr))

// ---------------- prepack wq/wk/wv -> transposed [l][3E][E] fp16 ----------------
__global__ void prepack_qkv(const float* __restrict__ wq,
                            const float* __restrict__ wk,
                            const float* __restrict__ wv) {
    int idx = blockIdx.x * blockDim.x + threadIdx.x;
    int total = NL_LAYERS * E3 * EMB;
    if (idx >= total) return;
    int l = idx / (E3 * EMB);
    int r = idx % (E3 * EMB);
    int c = r / EMB;               // n of 3E
    int e = r % EMB;               // k of E
    float v;
    if (c < EMB) {
        int h = c >> 6, d = c & 63;
        v = wq[(((size_t)l * N_HEADS + h) * EMB + e) * HEAD_DIM + d];
    } else if (c < 2 * EMB) {
        int c2 = c - EMB; int h = c2 >> 6, d = c2 & 63;
        v = wk[(((size_t)l * N_HEADS + h) * EMB + e) * HEAD_DIM + d];
    } else {
        int c2 = c - 2 * EMB; int h = c2 >> 6, d = c2 & 63;
        v = wv[(((size_t)l * N_HEADS + h) * EMB + e) * HEAD_DIM + d];
    }
    g_wqkv[idx] = __float2half(v);
}

// ---------------- tiled transpose + fp16 cvt: src[R][C] f32 -> dst[C][R] f16 ----
__global__ void transpose_cvt(const float* __restrict__ src, __half* __restrict__ dst,
                              int R, int C) {
    __shared__ float tile[32][33];
    int bx = blockIdx.x * 32;   // C offset
    int by = blockIdx.y * 32;   // R offset
    int tx = threadIdx.x, ty = threadIdx.y;   // 32 x 8
    #pragma unroll
    for (int i = 0; i < 32; i += 8)
        tile[ty + i][tx] = src[(size_t)(by + ty + i) * C + bx + tx];
    __syncthreads();
    #pragma unroll
    for (int i = 0; i < 32; i += 8)
        dst[(size_t)(bx + ty + i) * R + by + tx] = __float2half(tile[tx][ty + i]);
}

// ---------------- embedding ----------------
__global__ void embed_kernel(const int* __restrict__ ids,
                             const float* __restrict__ tok_emb,
                             const float* __restrict__ pos_emb) {
    int idx = blockIdx.x * blockDim.x + threadIdx.x;
    if (idx >= ROWS * EMB) return;
    int row = idx >> 10;
    int e   = idx & 1023;
    int t   = row & (SEQ_T - 1);
    int tok = ids[row];
    g_x[idx] = tok_emb[(size_t)tok * EMB + e] + pos_emb[(size_t)t * EMB + e];
}

// ---------------- layernorm (fp16 output: feeds GEMMs) ----------------
__global__ void ln_kernel(const float* __restrict__ in,
                          const float* __restrict__ gamma,
                          const float* __restrict__ beta,
                          __half* __restrict__ out) {
    int row = blockIdx.x;
    int tid = threadIdx.x;                 // 256 threads
    const float* p = in + (size_t)row * EMB;
    float s = 0.f, s2 = 0.f;
    #pragma unroll
    for (int i = 0; i < 4; i++) {
        float v = p[tid + i * 256];
        s += v; s2 += v * v;
    }
    __shared__ float rs[256], rs2[256];
    rs[tid] = s; rs2[tid] = s2;
    __syncthreads();
    for (int st = 128; st > 0; st >>= 1) {
        if (tid < st) { rs[tid] += rs[tid + st]; rs2[tid] += rs2[tid + st]; }
        __syncthreads();
    }
    float mu  = rs[0]  * (1.0f / EMB);
    float var = rs2[0] * (1.0f / EMB) - mu * mu;
    float inv = rsqrtf(var + LN_EPS);
    __half* o = out + (size_t)row * EMB;
    #pragma unroll
    for (int i = 0; i < 4; i++) {
        int e = tid + i * 256;
        o[e] = __float2half((p[e] - mu) * inv * gamma[e] + beta[e]);
    }
}

// ---------------- fp16 tensor-core GEMM (LDSM + SW128 swizzle) ----------------
// C/Ch[MxN] = A[MxK]f16 @ Bt[NxK]^T f16 (+bias)(+res)(relu)
// CTA 128x128x64, 8 warps (2m x 4n), warp tile 64x32, mma m16n8k16, ldmatrix.
// Tile rows are 64 halves = 128B = one SW128 atom; chunk' = chunk ^ (row & 7).
#define TBM 128
#define TBN 128
#define TBK 64
#define STG_BYTES 16384                    // one 128x128B tile
#define GEMM_SMEM (4 * STG_BYTES)          // 2 stages x (A + B)

__global__ __launch_bounds__(256, 2)
void hgemm(const __half* __restrict__ A, const __half* __restrict__ Bt,
           const float* __restrict__ bias, const float* __restrict__ res,
           float* __restrict__ C, __half* __restrict__ Ch,
           int M, int N, int K, int relu) {
    extern __shared__ char smraw[];
    const unsigned sbase = (unsigned)__cvta_generic_to_shared(smraw);

    const int tid  = threadIdx.x;
    const int lane = tid & 31;
    const int wid  = tid >> 5;
    const int wm   = (wid & 1) * 64;
    const int wn   = (wid >> 1) * 32;
    const int g    = lane >> 2;
    const int tg   = lane & 3;

    const int brow = blockIdx.y * TBM;
    const int bcol = blockIdx.x * TBN;

    const __half* Ag = A  + (size_t)brow * K;
    const __half* Bg = Bt + (size_t)bcol * K;

    // cp.async mapping: chunk = tid + i*256 over 1024; row = c>>3, j = c&7
    const int lrow = tid >> 3;
    const int ljc  = tid & 7;

    // ldmatrix per-lane geometry
    const int quad  = lane >> 3;           // 0..3
    const int lr8   = lane & 7;
    const int a_qh  = quad >> 1;           // k-chunk select for A
    const int a_rl  = (quad & 1) * 8;      // +8 rows for A quads 1,3
    const int b_ql  = quad & 1;            // k-chunk select for B
    const int b_rh  = (quad >> 1) * 8;     // +8 n-rows for B quads 2,3

    unsigned arow_off[4], arow_x[4], brow_off[2], brow_x[2];
    #pragma unroll
    for (int mt = 0; mt < 4; mt++) {
        int r = wm + mt * 16 + a_rl + lr8;
        arow_off[mt] = r * 128; arow_x[mt] = r & 7;
    }
    #pragma unroll
    for (int p = 0; p < 2; p++) {
        int r = wn + p * 16 + b_rh + lr8;
        brow_off[p] = r * 128; brow_x[p] = r & 7;
    }

    float acc[4][4][4];
    #pragma unroll
    for (int i = 0; i < 4; i++)
        #pragma unroll
        for (int j = 0; j < 4; j++)
            #pragma unroll
            for (int c = 0; c < 4; c++) acc[i][j][c] = 0.f;

    const int KT = K / TBK;

    #define LOAD_STAGE(stg, kt_) do {                                         \
        int k0 = (kt_) * TBK;                                                 \
        unsigned aB = sbase + (stg) * 2 * STG_BYTES;                          \
        unsigned bB = aB + STG_BYTES;                                         \
        _Pragma("unroll")                                                     \
        for (int i = 0; i < 4; i++) {                                         \
            int r = lrow + i * 32;                                            \
            unsigned sw = (unsigned)((ljc ^ (r & 7)) << 4) + r * 128;         \
            CP_ASYNC16(aB + sw, Ag + (size_t)r * K + k0 + ljc * 8);           \
            CP_ASYNC16(bB + sw, Bg + (size_t)r * K + k0 + ljc * 8);           \
        }                                                                     \
        CP_COMMIT();                                                          \
    } while (0)

    LOAD_STAGE(0, 0);

    for (int kt = 0; kt < KT; kt++) {
        const int cur = kt & 1;
        if (kt + 1 < KT) {
            LOAD_STAGE(cur ^ 1, kt + 1);
            CP_WAIT(1);
        } else {
            CP_WAIT(0);
        }
        __syncthreads();

        const unsigned aBase = sbase + cur * 2 * STG_BYTES;
        const unsigned bBase = aBase + STG_BYTES;

        #pragma unroll
        for (int ks = 0; ks < 4; ks++) {
            unsigned a_[4][4], b_[4][2];
            #pragma unroll
            for (int mt = 0; mt < 4; mt++) {
                unsigned addr = aBase + arow_off[mt] +
                    ((unsigned)(((2 * ks + a_qh) ^ arow_x[mt])) << 4);
                LDSM_X4(a_[mt][0], a_[mt][1], a_[mt][2], a_[mt][3], addr);
            }
            #pragma unroll
            for (int p = 0; p < 2; p++) {
                unsigned addr = bBase + brow_off[p] +
                    ((unsigned)(((2 * ks + b_ql) ^ brow_x[p])) << 4);
                unsigned r0, r1, r2, r3;
                LDSM_X4(r0, r1, r2, r3, addr);
                b_[2 * p][0] = r0;     b_[2 * p][1] = r1;
                b_[2 * p + 1][0] = r2; b_[2 * p + 1][1] = r3;
            }
            #pragma unroll
            for (int mt = 0; mt < 4; mt++)
                #pragma unroll
                for (int nt = 0; nt < 4; nt++)
                    MMA_F16(acc[mt][nt], a_[mt], b_[nt]);
        }
        __syncthreads();
    }

    // epilogue
    #pragma unroll
    for (int mt = 0; mt < 4; mt++) {
        int r0 = brow + wm + mt * 16 + g;
        #pragma unroll
        for (int nt = 0; nt < 4; nt++) {
            int c0 = bcol + wn + nt * 8 + tg * 2;
            float b0 = 0.f, b1 = 0.f;
            if (bias) { b0 = bias[c0]; b1 = bias[c0 + 1]; }
            #pragma unroll
            for (int half_ = 0; half_ < 2; half_++) {
                int r = r0 + half_ * 8;
                float v0 = acc[mt][nt][half_ * 2 + 0] + b0;
                float v1 = acc[mt][nt][half_ * 2 + 1] + b1;
                if (res) {
                    const float2 rr = *(const float2*)(res + (size_t)r * N + c0);
                    v0 += rr.x; v1 += rr.y;
                }
                if (relu) { v0 = fmaxf(v0, 0.f); v1 = fmaxf(v1, 0.f); }
                if (C) {
                    float2 o; o.x = v0; o.y = v1;
                    *(float2*)(C + (size_t)r * N + c0) = o;
                }
                if (Ch) {
                    __half2 oh = __floats2half2_rn(v0, v1);
                    *(__half2*)(Ch + (size_t)r * N + c0) = oh;
                }
            }
        }
    }
}

// ---------------- flash attention (fp32 compute, fp16 output) ----------------
#define KPAD 68
#define ATTN_SMEM ((64 * 64 + 3 * 64 * KPAD) * 4)

__global__ __launch_bounds__(256)
void flash_attn(const float* __restrict__ qkv, __half* __restrict__ att) {
    extern __shared__ float sm[];
    float* Qs = sm;
    float* Ks = sm + 64 * 64;
    float* Vs = Ks + 64 * KPAD;
    float* Ps = Vs + 64 * KPAD;

    const int qt  = blockIdx.x;
    const int h   = blockIdx.y;
    const int b   = blockIdx.z;
    const int tid = threadIdx.x;
    const int ty  = tid >> 4;
    const int tx  = tid & 15;

    #pragma unroll
    for (int i = 0; i < 4; i++) {
        int idx = tid + i * 256;
        int r = idx >> 4, c4 = (idx & 15) * 4;
        *(float4*)(Qs + r * 64 + c4) =
            *(const float4*)(qkv + (size_t)(b * SEQ_T + qt * 64 + r) * E3 +
                             h * HEAD_DIM + c4);
    }

    float m[4], l[4], O[4][4];
    #pragma unroll
    for (int i = 0; i < 4; i++) {
        m[i] = -1e30f; l[i] = 0.f;
        #pragma unroll
        for (int j = 0; j < 4; j++) O[i][j] = 0.f;
    }

    for (int kt = 0; kt <= qt; kt++) {
        #pragma unroll
        for (int i = 0; i < 4; i++) {
            int idx = tid + i * 256;
            int r = idx >> 4, c4 = (idx & 15) * 4;
            size_t base = (size_t)(b * SEQ_T + kt * 64 + r) * E3 + h * HEAD_DIM + c4;
            *(float4*)(Ks + r * KPAD + c4) = *(const float4*)(qkv + base + EMB);
            *(float4*)(Vs + r * KPAD + c4) = *(const float4*)(qkv + base + 2 * EMB);
        }
        __syncthreads();

        float s[4][4];
        #pragma unroll
        for (int i = 0; i < 4; i++)
            #pragma unroll
            for (int j = 0; j < 4; j++) s[i][j] = 0.f;
        #pragma unroll
        for (int d4 = 0; d4 < 16; d4++) {
            float4 q[4];
            #pragma unroll
            for (int i = 0; i < 4; i++)
                q[i] = *(const float4*)(Qs + (ty * 4 + i) * 64 + d4 * 4);
            #pragma unroll
            for (int j = 0; j < 4; j++) {
                float4 k = *(const float4*)(Ks + (tx + 16 * j) * KPAD + d4 * 4);
                #pragma unroll
                for (int i = 0; i < 4; i++)
                    s[i][j] += q[i].x * k.x + q[i].y * k.y + q[i].z * k.z + q[i].w * k.w;
            }
        }

        #pragma unroll
        for (int i = 0; i < 4; i++) {
            int grow = qt * 64 + ty * 4 + i;
            float mloc = -1e30f;
            #pragma unroll
            for (int j = 0; j < 4; j++) {
                int gcol = kt * 64 + tx + 16 * j;
                float sv = s[i][j] * ATT_SCALE;
                if (gcol > grow) sv = -1e30f;
                s[i][j] = sv;
                mloc = fmaxf(mloc, sv);
            }
            #pragma unroll
            for (int off = 8; off > 0; off >>= 1)
                mloc = fmaxf(mloc, __shfl_xor_sync(0xffffffffu, mloc, off, 16));
            float mnew = fmaxf(m[i], mloc);
            float corr = __expf(m[i] - mnew);
            float rs = 0.f;
            #pragma unroll
            for (int j = 0; j < 4; j++) {
                float p = __expf(s[i][j] - mnew);
                s[i][j] = p; rs += p;
            }
            #pragma unroll
            for (int off = 8; off > 0; off >>= 1)
                rs += __shfl_xor_sync(0xffffffffu, rs, off, 16);
            l[i] = l[i] * corr + rs;
            m[i] = mnew;
            #pragma unroll
            for (int j = 0; j < 4; j++) {
                O[i][j] *= corr;
                Ps[(ty * 4 + i) * KPAD + tx + 16 * j] = s[i][j];
            }
        }
        __syncthreads();

        #pragma unroll 4
        for (int c = 0; c < 64; c++) {
            float p[4], v[4];
            #pragma unroll
            for (int i = 0; i < 4; i++) p[i] = Ps[(ty * 4 + i) * KPAD + c];
            #pragma unroll
            for (int j = 0; j < 4; j++) v[j] = Vs[c * KPAD + tx + 16 * j];
            #pragma unroll
            for (int i = 0; i < 4; i++)
                #pragma unroll
                for (int j = 0; j < 4; j++)
                    O[i][j] += p[i] * v[j];
        }
        __syncthreads();
    }

    #pragma unroll
    for (int i = 0; i < 4; i++) {
        float inv = 1.0f / l[i];
        size_t rbase = (size_t)(b * SEQ_T + qt * 64 + ty * 4 + i) * EMB + h * HEAD_DIM;
        #pragma unroll
        for (int j = 0; j < 4; j++)
            att[rbase + tx + 16 * j] = __float2half(O[i][j] * inv);
    }
}

// ---------------- loss (single pass, online max/sum) ----------------
__global__ __launch_bounds__(256)
void loss_rows_kernel(const float* __restrict__ logits, const int* __restrict__ tgt) {
    int row = blockIdx.x;
    int tid = threadIdx.x;
    const float4* lp4 = (const float4*)(logits + (size_t)row * VOCAB);
    float m = -1e30f, s = 0.f;
    for (int i = tid; i < VOCAB / 4; i += 256) {
        float4 v = lp4[i];
        float mx = fmaxf(fmaxf(v.x, v.y), fmaxf(v.z, v.w));
        if (mx > m) { s *= __expf(m - mx); m = mx; }
        s += __expf(v.x - m) + __expf(v.y - m) + __expf(v.z - m) + __expf(v.w - m);
    }
    __shared__ float rm[256], rs[256];
    rm[tid] = m; rs[tid] = s;
    __syncthreads();
    for (int st = 128; st > 0; st >>= 1) {
        if (tid < st) {
            float m1 = rm[tid], m2 = rm[tid + st];
            float M = fmaxf(m1, m2);
            rs[tid] = rs[tid] * __expf(m1 - M) + rs[tid + st] * __expf(m2 - M);
            rm[tid] = M;
        }
        __syncthreads();
    }
    if (tid == 0) {
        const float* lp = logits + (size_t)row * VOCAB;
        g_rowloss[row] = -(lp[tgt[row]] - rm[0] - logf(rs[0]));
    }
}

__global__ __launch_bounds__(256)
void loss_final_kernel(float* __restrict__ out_loss) {
    int tid = threadIdx.x;
    __shared__ float red[256];
    float s = 0.f;
    #pragma unroll
    for (int i = 0; i < ROWS / 256; i++) s += g_rowloss[tid + i * 256];
    red[tid] = s; __syncthreads();
    for (int st = 128; st > 0; st >>= 1) {
        if (tid < st) red[tid] += red[tid + st];
        __syncthreads();
    }
    if (tid == 0) out_loss[0] = red[0] * (1.0f / ROWS);
}

// ---------------- launch ----------------
static void run_gemm(const __half* A, const __half* Bt, const float* bias,
                     const float* res, float* C, __half* Ch,
                     int M, int N, int K, int relu) {
    dim3 grid(N / TBN, M / TBM);
    hgemm<<<grid, 256, GEMM_SMEM>>>(A, Bt, bias, res, C, Ch, M, N, K, relu);
}

extern "C" void kernel_launch(void* const* d_in, const int* in_sizes, int n_in,
                              void* d_out, int out_size) {
    const int*   ids     = (const int*)  d_in[0];
    const int*   targets = (const int*)  d_in[1];
    const float* tok_emb = (const float*)d_in[2];
    const float* pos_emb = (const float*)d_in[3];
    const float* wq      = (const float*)d_in[4];
    const float* wk      = (const float*)d_in[5];
    const float* wv      = (const float*)d_in[6];
    const float* wo      = (const float*)d_in[7];
    const float* bo      = (const float*)d_in[8];
    const float* ln1_g   = (const float*)d_in[9];
    const float* ln1_b   = (const float*)d_in[10];
    const float* w1      = (const float*)d_in[11];
    const float* b1      = (const float*)d_in[12];
    const float* w2      = (const float*)d_in[13];
    const float* b2      = (const float*)d_in[14];
    const float* lnf_g   = (const float*)d_in[15];
    const float* lnf_b   = (const float*)d_in[16];
    const float* lm_w    = (const float*)d_in[17];
    const float* lm_b    = (const float*)d_in[18];

    static int attr_set = 0;
    if (!attr_set) {
        cudaFuncSetAttribute(hgemm, cudaFuncAttributeMaxDynamicSharedMemorySize,
                             GEMM_SMEM);
        cudaFuncSetAttribute(flash_attn, cudaFuncAttributeMaxDynamicSharedMemorySize,
                             ATTN_SMEM);
        attr_set = 1;
    }

    float*  x;    cudaGetSymbolAddress((void**)&x,    g_x);
    __half* h16;  cudaGetSymbolAddress((void**)&h16,  g_h16);
    float*  qkv;  cudaGetSymbolAddress((void**)&qkv,  g_qkv);
    __half* att16;cudaGetSymbolAddress((void**)&att16,g_att16);
    __half* ff16; cudaGetSymbolAddress((void**)&ff16, g_ff16);
    __half* wqkvp;cudaGetSymbolAddress((void**)&wqkvp,g_wqkv);
    __half* wop;  cudaGetSymbolAddress((void**)&wop,  g_wo);
    __half* w1p;  cudaGetSymbolAddress((void**)&w1p,  g_w1);
    __half* w2p;  cudaGetSymbolAddress((void**)&w2p,  g_w2);
    __half* lmwp; cudaGetSymbolAddress((void**)&lmwp, g_lmw);
    float*  glog; cudaGetSymbolAddress((void**)&glog, g_logits);

    const long long NLOG = (long long)ROWS * VOCAB;
    float* logits = ((long long)out_size >= NLOG) ? (float*)d_out : glog;

    // weight prep: transpose + fp16 cvt (per launch, deterministic)
    {
        int total = NL_LAYERS * E3 * EMB;
        prepack_qkv<<<(total + 255) / 256, 256>>>(wq, wk, wv);
        dim3 tb(32, 8);
        for (int l = 0; l < NL_LAYERS; l++) {
            transpose_cvt<<<dim3(EMB / 32, EMB / 32), tb>>>(
                wo + (size_t)l * EMB * EMB, wop + (size_t)l * EMB * EMB, EMB, EMB);
            transpose_cvt<<<dim3(FF_DIM / 32, EMB / 32), tb>>>(
                w1 + (size_t)l * EMB * FF_DIM, w1p + (size_t)l * EMB * FF_DIM,
                EMB, FF_DIM);
            transpose_cvt<<<dim3(EMB / 32, FF_DIM / 32), tb>>>(
                w2 + (size_t)l * FF_DIM * EMB, w2p + (size_t)l * FF_DIM * EMB,
                FF_DIM, EMB);
        }
        transpose_cvt<<<dim3(VOCAB / 32, EMB / 32), tb>>>(lm_w, lmwp, EMB, VOCAB);
    }

    // embedding
    embed_kernel<<<(ROWS * EMB + 255) / 256, 256>>>(ids, tok_emb, pos_emb);

    dim3 agrid(SEQ_T / 64, N_HEADS, BATCH);
    for (int l = 0; l < NL_LAYERS; l++) {
        const float* g1  = ln1_g + l * EMB;
        const float* bt1 = ln1_b + l * EMB;
        // h16 = f16(LN(x))
        ln_kernel<<<ROWS, 256>>>(x, g1, bt1, h16);
        // qkv = h @ Wqkv^T   (fp32 out, feeds attention)
        run_gemm(h16, wqkvp + (size_t)l * E3 * EMB, nullptr, nullptr, qkv, nullptr,
                 ROWS, E3, EMB, 0);
        // flash attention -> att16
        flash_attn<<<agrid, 256, ATTN_SMEM>>>(qkv, att16);
        // x = x + att @ wo + bo
        run_gemm(att16, wop + (size_t)l * EMB * EMB, bo + l * EMB, x, x, nullptr,
                 ROWS, EMB, EMB, 0);
        // h16 = f16(LN(x))
        ln_kernel<<<ROWS, 256>>>(x, g1, bt1, h16);
        // ff16 = f16(relu(h @ w1 + b1))
        run_gemm(h16, w1p + (size_t)l * EMB * FF_DIM, b1 + l * FF_DIM, nullptr,
                 nullptr, ff16, ROWS, FF_DIM, EMB, 1);
        // x = x + ff @ w2 + b2
        run_gemm(ff16, w2p + (size_t)l * FF_DIM * EMB, b2 + l * EMB, x, x, nullptr,
                 ROWS, EMB, FF_DIM, 0);
    }

    // final LN + lm head
    ln_kernel<<<ROWS, 256>>>(x, lnf_g, lnf_b, h16);
    run_gemm(h16, lmwp, lm_b, nullptr, logits, nullptr, ROWS, VOCAB, EMB, 0);

    // loss (deterministic reductions)
    if (out_size == 1 || (long long)out_size > NLOG) {
        loss_rows_kernel<<<ROWS, 256>>>(logits, targets);
        float* loss_dst = (out_size == 1) ? (float*)d_out
                                          : ((float*)d_out + NLOG);
        loss_final_kernel<<<1, 256>>>(loss_dst);
    }
}

// round 13
// speedup vs baseline: 2.5067x; 1.4210x over previous
#include <cuda_runtime.h>
#include <cuda_fp16.h>
#include <math.h>
#include <stdint.h>

// ---------------- problem constants ----------------
#define NL_LAYERS 3
#define N_HEADS   16
#define EMB       1024
#define HEAD_DIM  64
#define SEQ_T     1024
#define BATCH     4
#define ROWS      (BATCH * SEQ_T)      // 4096
#define VOCAB     32000
#define E3        (3 * EMB)            // 3072
#define FF_DIM    (4 * EMB)            // 4096
#define LN_EPS    1e-5f
#define ATT_SCALE 0.03125f             // 1/sqrt(EMB) = 1/32

// ---------------- scratch (device globals; no allocation allowed) ----------------
__device__ float  g_x   [ROWS * EMB];            // residual (fp32)
__device__ __half g_h16 [ROWS * EMB];            // LN output (fp16, GEMM A)
__device__ __half g_qkv16[ROWS * E3];            // qkv activations (fp16)
__device__ __half g_att16[ROWS * EMB];           // attention out (fp16, GEMM A)
__device__ __half g_ff16[ROWS * FF_DIM];         // FFN hidden (fp16, GEMM A)
__device__ __half g_wqkv[NL_LAYERS * E3 * EMB];  // transposed [3E][E] fp16
__device__ __half g_wo  [NL_LAYERS * EMB * EMB]; // transposed fp16
__device__ __half g_w1  [NL_LAYERS * FF_DIM * EMB];
__device__ __half g_w2  [NL_LAYERS * EMB * FF_DIM];
__device__ __half g_lmw [(size_t)VOCAB * EMB];
__device__ float  g_logits[(size_t)ROWS * VOCAB];
__device__ float  g_rowloss[ROWS];

// ---------------- async copy ----------------
#define CP_ASYNC16(dst, src)                                                  \
    asm volatile("cp.async.cg.shared.global [%0], [%1], 16;" ::               \
                 "r"(dst), "l"(src))
#define CP_COMMIT() asm volatile("cp.async.commit_group;")
#define CP_WAIT(n)  asm volatile("cp.async.wait_group %0;" :: "n"(n))

// fp16 mma: D(f32) += A(f16) @ B(f16), m16n8k16, row.col
#define MMA_F16(d, a, b)                                                      \
    asm volatile("mma.sync.aligned.m16n8k16.row.col.f32.f16.f16.f32 "         \
                 "{%0,%1,%2,%3}, {%4,%5,%6,%7}, {%8,%9}, {%0,%1,%2,%3};"      \
                 : "+f"(d[0]), "+f"(d[1]), "+f"(d[2]), "+f"(d[3])             \
                 : "r"(a[0]), "r"(a[1]), "r"(a[2]), "r"(a[3]),                \
                   "r"(b[0]), "r"(b[1]))

#define LDSM_X4(r0, r1, r2, r3, addr)                                         \
    asm volatile("ldmatrix.sync.aligned.m8n8.x4.shared.b16 {%0,%1,%2,%3}, [%4];" \
                 : "=r"(r0), "=r"(r1), "=r"(r2), "=r"(r3) : "r"(addr))
#define LDSM_X4_T(r0, r1, r2, r3, addr)                                       \
    asm volatile("ldmatrix.sync.aligned.m8n8.x4.trans.shared.b16 {%0,%1,%2,%3}, [%4];" \
                 : "=r"(r0), "=r"(r1), "=r"(r2), "=r"(r3) : "r"(addr))

__device__ __forceinline__ unsigned h2u(float a, float b) {
    __half2 h = __floats2half2_rn(a, b);
    return *(unsigned*)&h;
}

// ---------------- prepack wq/wk/wv -> transposed [l][3E][E] fp16 ----------------
__global__ void prepack_qkv(const float* __restrict__ wq,
                            const float* __restrict__ wk,
                            const float* __restrict__ wv) {
    int idx = blockIdx.x * blockDim.x + threadIdx.x;
    int total = NL_LAYERS * E3 * EMB;
    if (idx >= total) return;
    int l = idx / (E3 * EMB);
    int r = idx % (E3 * EMB);
    int c = r / EMB;               // n of 3E
    int e = r % EMB;               // k of E
    float v;
    if (c < EMB) {
        int h = c >> 6, d = c & 63;
        v = wq[(((size_t)l * N_HEADS + h) * EMB + e) * HEAD_DIM + d];
    } else if (c < 2 * EMB) {
        int c2 = c - EMB; int h = c2 >> 6, d = c2 & 63;
        v = wk[(((size_t)l * N_HEADS + h) * EMB + e) * HEAD_DIM + d];
    } else {
        int c2 = c - 2 * EMB; int h = c2 >> 6, d = c2 & 63;
        v = wv[(((size_t)l * N_HEADS + h) * EMB + e) * HEAD_DIM + d];
    }
    g_wqkv[idx] = __float2half(v);
}

// ---------------- tiled transpose + fp16 cvt: src[R][C] f32 -> dst[C][R] f16 ----
__global__ void transpose_cvt(const float* __restrict__ src, __half* __restrict__ dst,
                              int R, int C) {
    __shared__ float tile[32][33];
    int bx = blockIdx.x * 32;
    int by = blockIdx.y * 32;
    int tx = threadIdx.x, ty = threadIdx.y;   // 32 x 8
    #pragma unroll
    for (int i = 0; i < 32; i += 8)
        tile[ty + i][tx] = src[(size_t)(by + ty + i) * C + bx + tx];
    __syncthreads();
    #pragma unroll
    for (int i = 0; i < 32; i += 8)
        dst[(size_t)(bx + ty + i) * R + by + tx] = __float2half(tile[tx][ty + i]);
}

// ---------------- embedding ----------------
__global__ void embed_kernel(const int* __restrict__ ids,
                             const float* __restrict__ tok_emb,
                             const float* __restrict__ pos_emb) {
    int idx = blockIdx.x * blockDim.x + threadIdx.x;
    if (idx >= ROWS * EMB) return;
    int row = idx >> 10;
    int e   = idx & 1023;
    int t   = row & (SEQ_T - 1);
    int tok = ids[row];
    g_x[idx] = tok_emb[(size_t)tok * EMB + e] + pos_emb[(size_t)t * EMB + e];
}

// ---------------- layernorm (fp16 output: feeds GEMMs) ----------------
__global__ void ln_kernel(const float* __restrict__ in,
                          const float* __restrict__ gamma,
                          const float* __restrict__ beta,
                          __half* __restrict__ out) {
    int row = blockIdx.x;
    int tid = threadIdx.x;                 // 256 threads
    const float* p = in + (size_t)row * EMB;
    float s = 0.f, s2 = 0.f;
    #pragma unroll
    for (int i = 0; i < 4; i++) {
        float v = p[tid + i * 256];
        s += v; s2 += v * v;
    }
    __shared__ float rs[256], rs2[256];
    rs[tid] = s; rs2[tid] = s2;
    __syncthreads();
    for (int st = 128; st > 0; st >>= 1) {
        if (tid < st) { rs[tid] += rs[tid + st]; rs2[tid] += rs2[tid + st]; }
        __syncthreads();
    }
    float mu  = rs[0]  * (1.0f / EMB);
    float var = rs2[0] * (1.0f / EMB) - mu * mu;
    float inv = rsqrtf(var + LN_EPS);
    __half* o = out + (size_t)row * EMB;
    #pragma unroll
    for (int i = 0; i < 4; i++) {
        int e = tid + i * 256;
        o[e] = __float2half((p[e] - mu) * inv * gamma[e] + beta[e]);
    }
}

// ---------------- fp16 tensor-core GEMM (LDSM + SW128 swizzle) ----------------
#define TBM 128
#define TBN 128
#define TBK 64
#define STG_BYTES 16384
#define GEMM_SMEM (4 * STG_BYTES)

__global__ __launch_bounds__(256, 2)
void hgemm(const __half* __restrict__ A, const __half* __restrict__ Bt,
           const float* __restrict__ bias, const float* __restrict__ res,
           float* __restrict__ C, __half* __restrict__ Ch,
           int M, int N, int K, int relu) {
    extern __shared__ char smraw[];
    const unsigned sbase = (unsigned)__cvta_generic_to_shared(smraw);

    const int tid  = threadIdx.x;
    const int lane = tid & 31;
    const int wid  = tid >> 5;
    const int wm   = (wid & 1) * 64;
    const int wn   = (wid >> 1) * 32;
    const int g    = lane >> 2;
    const int tg   = lane & 3;

    const int brow = blockIdx.y * TBM;
    const int bcol = blockIdx.x * TBN;

    const __half* Ag = A  + (size_t)brow * K;
    const __half* Bg = Bt + (size_t)bcol * K;

    const int lrow = tid >> 3;
    const int ljc  = tid & 7;

    const int quad  = lane >> 3;
    const int lr8   = lane & 7;
    const int a_qh  = quad >> 1;
    const int a_rl  = (quad & 1) * 8;
    const int b_ql  = quad & 1;
    const int b_rh  = (quad >> 1) * 8;

    unsigned arow_off[4], arow_x[4], brow_off[2], brow_x[2];
    #pragma unroll
    for (int mt = 0; mt < 4; mt++) {
        int r = wm + mt * 16 + a_rl + lr8;
        arow_off[mt] = r * 128; arow_x[mt] = r & 7;
    }
    #pragma unroll
    for (int p = 0; p < 2; p++) {
        int r = wn + p * 16 + b_rh + lr8;
        brow_off[p] = r * 128; brow_x[p] = r & 7;
    }

    float acc[4][4][4];
    #pragma unroll
    for (int i = 0; i < 4; i++)
        #pragma unroll
        for (int j = 0; j < 4; j++)
            #pragma unroll
            for (int c = 0; c < 4; c++) acc[i][j][c] = 0.f;

    const int KT = K / TBK;

    #define LOAD_STAGE(stg, kt_) do {                                         \
        int k0 = (kt_) * TBK;                                                 \
        unsigned aB = sbase + (stg) * 2 * STG_BYTES;                          \
        unsigned bB = aB + STG_BYTES;                                         \
        _Pragma("unroll")                                                     \
        for (int i = 0; i < 4; i++) {                                         \
            int r = lrow + i * 32;                                            \
            unsigned sw = (unsigned)((ljc ^ (r & 7)) << 4) + r * 128;         \
            CP_ASYNC16(aB + sw, Ag + (size_t)r * K + k0 + ljc * 8);           \
            CP_ASYNC16(bB + sw, Bg + (size_t)r * K + k0 + ljc * 8);           \
        }                                                                     \
        CP_COMMIT();                                                          \
    } while (0)

    LOAD_STAGE(0, 0);

    for (int kt = 0; kt < KT; kt++) {
        const int cur = kt & 1;
        if (kt + 1 < KT) {
            LOAD_STAGE(cur ^ 1, kt + 1);
            CP_WAIT(1);
        } else {
            CP_WAIT(0);
        }
        __syncthreads();

        const unsigned aBase = sbase + cur * 2 * STG_BYTES;
        const unsigned bBase = aBase + STG_BYTES;

        #pragma unroll
        for (int ks = 0; ks < 4; ks++) {
            unsigned a_[4][4], b_[4][2];
            #pragma unroll
            for (int mt = 0; mt < 4; mt++) {
                unsigned addr = aBase + arow_off[mt] +
                    ((unsigned)(((2 * ks + a_qh) ^ arow_x[mt])) << 4);
                LDSM_X4(a_[mt][0], a_[mt][1], a_[mt][2], a_[mt][3], addr);
            }
            #pragma unroll
            for (int p = 0; p < 2; p++) {
                unsigned addr = bBase + brow_off[p] +
                    ((unsigned)(((2 * ks + b_ql) ^ brow_x[p])) << 4);
                unsigned r0, r1, r2, r3;
                LDSM_X4(r0, r1, r2, r3, addr);
                b_[2 * p][0] = r0;     b_[2 * p][1] = r1;
                b_[2 * p + 1][0] = r2; b_[2 * p + 1][1] = r3;
            }
            #pragma unroll
            for (int mt = 0; mt < 4; mt++)
                #pragma unroll
                for (int nt = 0; nt < 4; nt++)
                    MMA_F16(acc[mt][nt], a_[mt], b_[nt]);
        }
        __syncthreads();
    }

    #pragma unroll
    for (int mt = 0; mt < 4; mt++) {
        int r0 = brow + wm + mt * 16 + g;
        #pragma unroll
        for (int nt = 0; nt < 4; nt++) {
            int c0 = bcol + wn + nt * 8 + tg * 2;
            float b0 = 0.f, b1 = 0.f;
            if (bias) { b0 = bias[c0]; b1 = bias[c0 + 1]; }
            #pragma unroll
            for (int half_ = 0; half_ < 2; half_++) {
                int r = r0 + half_ * 8;
                float v0 = acc[mt][nt][half_ * 2 + 0] + b0;
                float v1 = acc[mt][nt][half_ * 2 + 1] + b1;
                if (res) {
                    const float2 rr = *(const float2*)(res + (size_t)r * N + c0);
                    v0 += rr.x; v1 += rr.y;
                }
                if (relu) { v0 = fmaxf(v0, 0.f); v1 = fmaxf(v1, 0.f); }
                if (C) {
                    float2 o; o.x = v0; o.y = v1;
                    *(float2*)(C + (size_t)r * N + c0) = o;
                }
                if (Ch) {
                    __half2 oh = __floats2half2_rn(v0, v1);
                    *(__half2*)(Ch + (size_t)r * N + c0) = oh;
                }
            }
        }
    }
}

// ---------------- tensor-core flash attention ----------------
// grid (T/64, H, B), 128 threads (4 warps x 16 q-rows).
// Q,K,V fp16 tiles 64x64 (128B rows, SW128). S=Q@K^T and O+=P@V via m16n8k16.
// K: non-trans ldmatrix ([s][d] == B's [n][k]); V: trans ldmatrix (V^T).
#define FA_SMEM (5 * 8192)   // Q + 2*(K+V)

__global__ __launch_bounds__(128)
void flash_attn_tc(const __half* __restrict__ qkv, __half* __restrict__ att) {
    extern __shared__ char smraw[];
    const unsigned sbase = (unsigned)__cvta_generic_to_shared(smraw);
    const unsigned sQ = sbase;

    const int qt = blockIdx.x, h = blockIdx.y, b = blockIdx.z;
    const int tid  = threadIdx.x;
    const int lane = tid & 31;
    const int w    = tid >> 5;
    const int g    = lane >> 2;
    const int tg   = lane & 3;
    const int li   = lane >> 3;        // ldmatrix matrix index
    const int lr8  = lane & 7;

    const __half* qbase = qkv + (size_t)(b * SEQ_T) * E3 + h * HEAD_DIM;
    const __half* kbase = qbase + EMB;
    const __half* vbase = qbase + 2 * EMB;

    // Q tile load (cp.async, swizzled): thread t -> row t>>1, chunks (t&1)*4+i
    {
        int r = tid >> 1, c0 = (tid & 1) * 4;
        const __half* src = qbase + (size_t)(qt * 64 + r) * E3;
        #pragma unroll
        for (int i = 0; i < 4; i++) {
            int c = c0 + i;
            CP_ASYNC16(sQ + r * 128 + ((c ^ (r & 7)) << 4), src + c * 8);
        }
        CP_COMMIT();
    }

    #define FA_LOADKV(stg, kt_) do {                                          \
        unsigned kB = sbase + 8192 + (stg) * 16384;                           \
        unsigned vB = kB + 8192;                                              \
        int r = tid >> 1, c0 = (tid & 1) * 4;                                 \
        const __half* ksrc = kbase + (size_t)((kt_) * 64 + r) * E3;           \
        const __half* vsrc = vbase + (size_t)((kt_) * 64 + r) * E3;           \
        _Pragma("unroll")                                                     \
        for (int i = 0; i < 4; i++) {                                         \
            int c = c0 + i;                                                   \
            unsigned swo = r * 128 + ((c ^ (r & 7)) << 4);                    \
            CP_ASYNC16(kB + swo, ksrc + c * 8);                               \
            CP_ASYNC16(vB + swo, vsrc + c * 8);                               \
        }                                                                     \
        CP_COMMIT();                                                          \
    } while (0)

    FA_LOADKV(0, 0);

    float S[8][4], O[8][4];
    float mrow[2] = {-1e30f, -1e30f}, lrow[2] = {0.f, 0.f};
    #pragma unroll
    for (int n = 0; n < 8; n++)
        #pragma unroll
        for (int c = 0; c < 4; c++) O[n][c] = 0.f;
    unsigned Qf[4][4];

    const int qrow0 = qt * 64 + w * 16 + g;

    for (int kt = 0; kt <= qt; kt++) {
        if (kt < qt) { FA_LOADKV((kt + 1) & 1, kt + 1); CP_WAIT(1); }
        else         { CP_WAIT(0); }
        __syncthreads();

        const unsigned kB = sbase + 8192 + (kt & 1) * 16384;
        const unsigned vB = kB + 8192;

        if (kt == 0) {
            // Q fragments: mat i -> rows w*16 + (i&1)*8, chunk 2q + (i>>1)
            #pragma unroll
            for (int q = 0; q < 4; q++) {
                int r = w * 16 + ((li & 1) << 3) + lr8;
                int c = 2 * q + (li >> 1);
                unsigned addr = sQ + r * 128 + ((c ^ (r & 7)) << 4);
                LDSM_X4(Qf[q][0], Qf[q][1], Qf[q][2], Qf[q][3], addr);
            }
        }

        // S = Q @ K^T
        #pragma unroll
        for (int n = 0; n < 8; n++)
            #pragma unroll
            for (int c = 0; c < 4; c++) S[n][c] = 0.f;
        #pragma unroll
        for (int q = 0; q < 4; q++) {
            #pragma unroll
            for (int jp = 0; jp < 4; jp++) {
                // mat i -> s rows 16jp + (i>>1)*8, chunk 2q + (i&1)
                int r = 16 * jp + ((li >> 1) << 3) + lr8;
                int c = 2 * q + (li & 1);
                unsigned addr = kB + r * 128 + ((c ^ (r & 7)) << 4);
                unsigned k0, k1, k2, k3;
                LDSM_X4(k0, k1, k2, k3, addr);
                unsigned bb0[2] = {k0, k1}, bb1[2] = {k2, k3};
                MMA_F16(S[2 * jp],     Qf[q], bb0);
                MMA_F16(S[2 * jp + 1], Qf[q], bb1);
            }
        }

        // online softmax on fragments
        float mloc0 = -1e30f, mloc1 = -1e30f;
        #pragma unroll
        for (int j = 0; j < 8; j++) {
            int scol = kt * 64 + 8 * j + 2 * tg;
            float s0 = S[j][0] * ATT_SCALE, s1 = S[j][1] * ATT_SCALE;
            float s2 = S[j][2] * ATT_SCALE, s3 = S[j][3] * ATT_SCALE;
            if (scol     > qrow0)     s0 = -1e30f;
            if (scol + 1 > qrow0)     s1 = -1e30f;
            if (scol     > qrow0 + 8) s2 = -1e30f;
            if (scol + 1 > qrow0 + 8) s3 = -1e30f;
            S[j][0] = s0; S[j][1] = s1; S[j][2] = s2; S[j][3] = s3;
            mloc0 = fmaxf(mloc0, fmaxf(s0, s1));
            mloc1 = fmaxf(mloc1, fmaxf(s2, s3));
        }
        #pragma unroll
        for (int off = 1; off <= 2; off <<= 1) {
            mloc0 = fmaxf(mloc0, __shfl_xor_sync(0xffffffffu, mloc0, off));
            mloc1 = fmaxf(mloc1, __shfl_xor_sync(0xffffffffu, mloc1, off));
        }
        float mn0 = fmaxf(mrow[0], mloc0), mn1 = fmaxf(mrow[1], mloc1);
        float corr0 = __expf(mrow[0] - mn0), corr1 = __expf(mrow[1] - mn1);
        mrow[0] = mn0; mrow[1] = mn1;

        unsigned Pf[4][4];
        float rs0 = 0.f, rs1 = 0.f;
        #pragma unroll
        for (int j = 0; j < 8; j++) {
            float p0 = __expf(S[j][0] - mn0);
            float p1 = __expf(S[j][1] - mn0);
            float p2 = __expf(S[j][2] - mn1);
            float p3 = __expf(S[j][3] - mn1);
            rs0 += p0 + p1; rs1 += p2 + p3;
            int q = j >> 1, lohi = (j & 1) << 1;
            Pf[q][lohi]     = h2u(p0, p1);
            Pf[q][lohi + 1] = h2u(p2, p3);
        }
        #pragma unroll
        for (int off = 1; off <= 2; off <<= 1) {
            rs0 += __shfl_xor_sync(0xffffffffu, rs0, off);
            rs1 += __shfl_xor_sync(0xffffffffu, rs1, off);
        }
        lrow[0] = lrow[0] * corr0 + rs0;
        lrow[1] = lrow[1] * corr1 + rs1;
        #pragma unroll
        for (int n = 0; n < 8; n++) {
            O[n][0] *= corr0; O[n][1] *= corr0;
            O[n][2] *= corr1; O[n][3] *= corr1;
        }

        // wait: Pf index fix — A frag order is {a0,a1,a2,a3} =
        // (m0-7,k0-7),(m8-15,k0-7),(m0-7,k8-15),(m8-15,k8-15):
        // j=2q  -> a0 = (c0,c1), a1 = (c2,c3);  j=2q+1 -> a2, a3.
        // The loop above packs Pf[q][0]=j even (c0,c1), Pf[q][1]=j even (c2,c3),
        // Pf[q][2]=j odd (c0,c1), Pf[q][3]=j odd (c2,c3)  ->  correct order.

        // O += P @ V   (V^T fragments via ldmatrix.trans)
        #pragma unroll
        for (int q = 0; q < 4; q++) {
            #pragma unroll
            for (int np = 0; np < 4; np++) {
                // mat i -> s rows 16q + (i&1)*8, chunk 2np + (i>>1)
                int r = 16 * q + ((li & 1) << 3) + lr8;
                int c = 2 * np + (li >> 1);
                unsigned addr = vB + r * 128 + ((c ^ (r & 7)) << 4);
                unsigned v0, v1, v2, v3;
                LDSM_X4_T(v0, v1, v2, v3, addr);
                unsigned bb0[2] = {v0, v1}, bb1[2] = {v2, v3};
                MMA_F16(O[2 * np],     Pf[q], bb0);
                MMA_F16(O[2 * np + 1], Pf[q], bb1);
            }
        }
        __syncthreads();
    }

    // write out fp16
    float inv0 = 1.0f / lrow[0], inv1 = 1.0f / lrow[1];
    __half* obase = att + (size_t)(b * SEQ_T + qt * 64 + w * 16 + g) * EMB +
                    h * HEAD_DIM;
    #pragma unroll
    for (int n = 0; n < 8; n++) {
        int d = 8 * n + 2 * tg;
        __half2 o0 = __floats2half2_rn(O[n][0] * inv0, O[n][1] * inv0);
        __half2 o1 = __floats2half2_rn(O[n][2] * inv1, O[n][3] * inv1);
        *(__half2*)(obase + d) = o0;
        *(__half2*)(obase + (size_t)8 * EMB + d) = o1;
    }
}

// ---------------- loss (single pass, online max/sum) ----------------
__global__ __launch_bounds__(256)
void loss_rows_kernel(const float* __restrict__ logits, const int* __restrict__ tgt) {
    int row = blockIdx.x;
    int tid = threadIdx.x;
    const float4* lp4 = (const float4*)(logits + (size_t)row * VOCAB);
    float m = -1e30f, s = 0.f;
    for (int i = tid; i < VOCAB / 4; i += 256) {
        float4 v = lp4[i];
        float mx = fmaxf(fmaxf(v.x, v.y), fmaxf(v.z, v.w));
        if (mx > m) { s *= __expf(m - mx); m = mx; }
        s += __expf(v.x - m) + __expf(v.y - m) + __expf(v.z - m) + __expf(v.w - m);
    }
    __shared__ float rm[256], rs[256];
    rm[tid] = m; rs[tid] = s;
    __syncthreads();
    for (int st = 128; st > 0; st >>= 1) {
        if (tid < st) {
            float m1 = rm[tid], m2 = rm[tid + st];
            float M = fmaxf(m1, m2);
            rs[tid] = rs[tid] * __expf(m1 - M) + rs[tid + st] * __expf(m2 - M);
            rm[tid] = M;
        }
        __syncthreads();
    }
    if (tid == 0) {
        const float* lp = logits + (size_t)row * VOCAB;
        g_rowloss[row] = -(lp[tgt[row]] - rm[0] - logf(rs[0]));
    }
}

__global__ __launch_bounds__(256)
void loss_final_kernel(float* __restrict__ out_loss) {
    int tid = threadIdx.x;
    __shared__ float red[256];
    float s = 0.f;
    #pragma unroll
    for (int i = 0; i < ROWS / 256; i++) s += g_rowloss[tid + i * 256];
    red[tid] = s; __syncthreads();
    for (int st = 128; st > 0; st >>= 1) {
        if (tid < st) red[tid] += red[tid + st];
        __syncthreads();
    }
    if (tid == 0) out_loss[0] = red[0] * (1.0f / ROWS);
}

// ---------------- launch ----------------
static void run_gemm(const __half* A, const __half* Bt, const float* bias,
                     const float* res, float* C, __half* Ch,
                     int M, int N, int K, int relu) {
    dim3 grid(N / TBN, M / TBM);
    hgemm<<<grid, 256, GEMM_SMEM>>>(A, Bt, bias, res, C, Ch, M, N, K, relu);
}

extern "C" void kernel_launch(void* const* d_in, const int* in_sizes, int n_in,
                              void* d_out, int out_size) {
    const int*   ids     = (const int*)  d_in[0];
    const int*   targets = (const int*)  d_in[1];
    const float* tok_emb = (const float*)d_in[2];
    const float* pos_emb = (const float*)d_in[3];
    const float* wq      = (const float*)d_in[4];
    const float* wk      = (const float*)d_in[5];
    const float* wv      = (const float*)d_in[6];
    const float* wo      = (const float*)d_in[7];
    const float* bo      = (const float*)d_in[8];
    const float* ln1_g   = (const float*)d_in[9];
    const float* ln1_b   = (const float*)d_in[10];
    const float* w1      = (const float*)d_in[11];
    const float* b1      = (const float*)d_in[12];
    const float* w2      = (const float*)d_in[13];
    const float* b2      = (const float*)d_in[14];
    const float* lnf_g   = (const float*)d_in[15];
    const float* lnf_b   = (const float*)d_in[16];
    const float* lm_w    = (const float*)d_in[17];
    const float* lm_b    = (const float*)d_in[18];

    static int attr_set = 0;
    if (!attr_set) {
        cudaFuncSetAttribute(hgemm, cudaFuncAttributeMaxDynamicSharedMemorySize,
                             GEMM_SMEM);
        cudaFuncSetAttribute(flash_attn_tc, cudaFuncAttributeMaxDynamicSharedMemorySize,
                             FA_SMEM);
        attr_set = 1;
    }

    float*  x;    cudaGetSymbolAddress((void**)&x,    g_x);
    __half* h16;  cudaGetSymbolAddress((void**)&h16,  g_h16);
    __half* qkv16;cudaGetSymbolAddress((void**)&qkv16,g_qkv16);
    __half* att16;cudaGetSymbolAddress((void**)&att16,g_att16);
    __half* ff16; cudaGetSymbolAddress((void**)&ff16, g_ff16);
    __half* wqkvp;cudaGetSymbolAddress((void**)&wqkvp,g_wqkv);
    __half* wop;  cudaGetSymbolAddress((void**)&wop,  g_wo);
    __half* w1p;  cudaGetSymbolAddress((void**)&w1p,  g_w1);
    __half* w2p;  cudaGetSymbolAddress((void**)&w2p,  g_w2);
    __half* lmwp; cudaGetSymbolAddress((void**)&lmwp, g_lmw);
    float*  glog; cudaGetSymbolAddress((void**)&glog, g_logits);

    const long long NLOG = (long long)ROWS * VOCAB;
    float* logits = ((long long)out_size >= NLOG) ? (float*)d_out : glog;

    // weight prep: transpose + fp16 cvt
    {
        int total = NL_LAYERS * E3 * EMB;
        prepack_qkv<<<(total + 255) / 256, 256>>>(wq, wk, wv);
        dim3 tb(32, 8);
        for (int l = 0; l < NL_LAYERS; l++) {
            transpose_cvt<<<dim3(EMB / 32, EMB / 32), tb>>>(
                wo + (size_t)l * EMB * EMB, wop + (size_t)l * EMB * EMB, EMB, EMB);
            transpose_cvt<<<dim3(FF_DIM / 32, EMB / 32), tb>>>(
                w1 + (size_t)l * EMB * FF_DIM, w1p + (size_t)l * EMB * FF_DIM,
                EMB, FF_DIM);
            transpose_cvt<<<dim3(EMB / 32, FF_DIM / 32), tb>>>(
                w2 + (size_t)l * FF_DIM * EMB, w2p + (size_t)l * FF_DIM * EMB,
                FF_DIM, EMB);
        }
        transpose_cvt<<<dim3(VOCAB / 32, EMB / 32), tb>>>(lm_w, lmwp, EMB, VOCAB);
    }

    // embedding
    embed_kernel<<<(ROWS * EMB + 255) / 256, 256>>>(ids, tok_emb, pos_emb);

    dim3 agrid(SEQ_T / 64, N_HEADS, BATCH);
    for (int l = 0; l < NL_LAYERS; l++) {
        const float* g1  = ln1_g + l * EMB;
        const float* bt1 = ln1_b + l * EMB;
        // h16 = f16(LN(x))
        ln_kernel<<<ROWS, 256>>>(x, g1, bt1, h16);
        // qkv16 = f16(h @ Wqkv^T)
        run_gemm(h16, wqkvp + (size_t)l * E3 * EMB, nullptr, nullptr, nullptr,
                 qkv16, ROWS, E3, EMB, 0);
        // tensor-core flash attention -> att16
        flash_attn_tc<<<agrid, 128, FA_SMEM>>>(qkv16, att16);
        // x = x + att @ wo + bo
        run_gemm(att16, wop + (size_t)l * EMB * EMB, bo + l * EMB, x, x, nullptr,
                 ROWS, EMB, EMB, 0);
        // h16 = f16(LN(x))
        ln_kernel<<<ROWS, 256>>>(x, g1, bt1, h16);
        // ff16 = f16(relu(h @ w1 + b1))
        run_gemm(h16, w1p + (size_t)l * EMB * FF_DIM, b1 + l * FF_DIM, nullptr,
                 nullptr, ff16, ROWS, FF_DIM, EMB, 1);
        // x = x + ff @ w2 + b2
        run_gemm(ff16, w2p + (size_t)l * FF_DIM * EMB, b2 + l * EMB, x, x, nullptr,
                 ROWS, EMB, FF_DIM, 0);
    }

    // final LN + lm head
    ln_kernel<<<ROWS, 256>>>(x, lnf_g, lnf_b, h16);
    run_gemm(h16, lmwp, lm_b, nullptr, logits, nullptr, ROWS, VOCAB, EMB, 0);

    // loss
    if (out_size == 1 || (long long)out_size > NLOG) {
        loss_rows_kernel<<<ROWS, 256>>>(logits, targets);
        float* loss_dst = (out_size == 1) ? (float*)d_out
                                          : ((float*)d_out + NLOG);
        loss_final_kernel<<<1, 256>>>(loss_dst);
    }
}